// round 13
// baseline (speedup 1.0000x reference)
#include <cuda_runtime.h>
#include <math.h>
#include <stdint.h>

// ---------------- problem constants ----------------
#define BB   4
#define NQ   900
#define DD   256
#define HH   8
#define HDD  32
#define LL   4
#define PP   4
#define SS   21760          // 128^2+64^2+32^2+16^2
#define DFF  1024
#define BNQ  (BB*NQ)        // 3600

// ---------------- device scratch ----------------
__device__ float g_qk [BNQ*512];
__device__ float g_v  [BNQ*DD];
__device__ float g_sa [BNQ*DD];
__device__ float g_tmp[BNQ*DD];
__device__ float g_t1 [BNQ*DD];
__device__ float g_t2 [BNQ*DD];
__device__ float g_off[BNQ*DD];
__device__ float g_acc[BNQ*DD];
__device__ float g_aw [BNQ*128];
__device__ float g_val[(long)BB*SS*DD];
__device__ float g_ffh[BNQ*DFF];

// ---------------- tf32 helpers ----------------
__device__ __forceinline__ float to_tf32(float x) {
    uint32_t o;
    asm("cvt.rna.tf32.f32 %0, %1;" : "=r"(o) : "f"(x));
    return __uint_as_float(o);
}

__device__ __forceinline__ void mma_tf32(float c[4],
                                         uint32_t a0, uint32_t a1, uint32_t a2, uint32_t a3,
                                         uint32_t b0, uint32_t b1) {
    asm volatile(
        "mma.sync.aligned.m16n8k8.row.col.f32.tf32.tf32.f32 "
        "{%0,%1,%2,%3}, {%4,%5,%6,%7}, {%8,%9}, {%0,%1,%2,%3};\n"
        : "+f"(c[0]), "+f"(c[1]), "+f"(c[2]), "+f"(c[3])
        : "r"(a0), "r"(a1), "r"(a2), "r"(a3), "r"(b0), "r"(b1));
}

// ---------------- TF32 GEMM: 4 warps, 64x64 warp tiles, double-buffered ----------------
// CTA tile 128x128x16, 128 threads. Raw fp32 regs into tf32 mma (HW truncation).
#define BM 128
#define BN 128
#define BKg 16
#define LDS_P 136   // ==8 mod 32 -> conflict-free fragment reads

template<int RELU, int MASK, int ADDA>
__global__ void __launch_bounds__(128, 2)
gemm_tc(const float* __restrict__ A, const float* __restrict__ A2, int lda,
        const float* __restrict__ W, int ldw,
        const float* __restrict__ bias,
        float* __restrict__ C, int ldc,
        int M, int N, int K,
        const unsigned char* __restrict__ mask) {
    __shared__ float As[2][BKg][LDS_P];
    __shared__ float Bs[2][BKg][LDS_P];

    const int t    = threadIdx.x;
    const int lane = t & 31;
    const int wid  = t >> 5;             // 0..3
    const int l4 = lane & 3, l2 = lane >> 2;
    const int warpM = (wid >> 1) * 64;   // 0,64
    const int warpN = (wid & 1) * 64;    // 0,64
    const int m0b = blockIdx.y * BM;
    const int n0b = blockIdx.x * BN;

    float acc[4][8][4];
    #pragma unroll
    for (int i = 0; i < 4; i++)
        #pragma unroll
        for (int j = 0; j < 8; j++)
            #pragma unroll
            for (int r = 0; r < 4; r++) acc[i][j][r] = 0.f;

    // loaders: thread t owns A row t (16 k-floats), and B row t>>3, cols (t&7)*16..+15
    const int bkr = t >> 3;
    const int bnc = (t & 7) * 16;

    float4 ra[4], rb[4];

    auto ldg = [&](int k0) {
        int gm = m0b + t;
        if (gm < M) {
            const float* p = A + (long)gm * lda + k0;
            #pragma unroll
            for (int c = 0; c < 4; c++) ra[c] = *(const float4*)(p + 4 * c);
            if (ADDA) {
                const float* p2 = A2 + (long)gm * lda + k0;
                #pragma unroll
                for (int c = 0; c < 4; c++) {
                    float4 s = *(const float4*)(p2 + 4 * c);
                    ra[c].x += s.x; ra[c].y += s.y; ra[c].z += s.z; ra[c].w += s.w;
                }
            }
        } else {
            #pragma unroll
            for (int c = 0; c < 4; c++) ra[c] = make_float4(0.f, 0.f, 0.f, 0.f);
        }
        const float* q = W + (long)(k0 + bkr) * ldw + n0b + bnc;
        #pragma unroll
        for (int c = 0; c < 4; c++) rb[c] = *(const float4*)(q + 4 * c);
    };

    auto sts = [&](int s) {
        #pragma unroll
        for (int c = 0; c < 4; c++) {
            As[s][4 * c + 0][t] = ra[c].x;
            As[s][4 * c + 1][t] = ra[c].y;
            As[s][4 * c + 2][t] = ra[c].z;
            As[s][4 * c + 3][t] = ra[c].w;
            *(float4*)&Bs[s][bkr][bnc + 4 * c] = rb[c];
        }
    };

    const int nt = K / BKg;
    ldg(0);
    sts(0);
    if (nt > 1) ldg(BKg);
    __syncthreads();

    int s = 0;
    for (int it = 0; it < nt; it++) {
        #pragma unroll
        for (int ks = 0; ks < 2; ks++) {
            const int kr = ks * 8 + l4;
            const int mo = warpM + l2;
            uint32_t af[4][4];
            #pragma unroll
            for (int i = 0; i < 4; i++) {
                af[i][0] = __float_as_uint(As[s][kr    ][mo + 16 * i    ]);
                af[i][1] = __float_as_uint(As[s][kr    ][mo + 16 * i + 8]);
                af[i][2] = __float_as_uint(As[s][kr + 4][mo + 16 * i    ]);
                af[i][3] = __float_as_uint(As[s][kr + 4][mo + 16 * i + 8]);
            }
            uint32_t bf[8][2];
            const int no = warpN + l2;
            #pragma unroll
            for (int j = 0; j < 8; j++) {
                bf[j][0] = __float_as_uint(Bs[s][kr    ][no + 8 * j]);
                bf[j][1] = __float_as_uint(Bs[s][kr + 4][no + 8 * j]);
            }
            #pragma unroll
            for (int i = 0; i < 4; i++)
                #pragma unroll
                for (int j = 0; j < 8; j++)
                    mma_tf32(acc[i][j], af[i][0], af[i][1], af[i][2], af[i][3],
                             bf[j][0], bf[j][1]);
        }
        if (it + 1 < nt) sts(s ^ 1);
        __syncthreads();
        if (it + 2 < nt) ldg((it + 2) * BKg);
        s ^= 1;
    }

    #pragma unroll
    for (int i = 0; i < 4; i++) {
        #pragma unroll
        for (int half = 0; half < 2; half++) {
            int gm = m0b + warpM + 16 * i + l2 + half * 8;
            if (gm >= M) continue;
            bool mz = MASK ? (mask[gm] != 0) : false;
            #pragma unroll
            for (int j = 0; j < 8; j++) {
                int gn = n0b + warpN + 8 * j + 2 * l4;
                float v0 = acc[i][j][half * 2 + 0] + bias[gn];
                float v1 = acc[i][j][half * 2 + 1] + bias[gn + 1];
                if (RELU) { v0 = fmaxf(v0, 0.f); v1 = fmaxf(v1, 0.f); }
                if (mz)   { v0 = 0.f; v1 = 0.f; }
                *(float2*)(C + (long)gm * ldc + gn) = make_float2(v0, v1);
            }
        }
    }
}

// ---------------- tensor-core flash attention (dynamic smem) ----------------
#define KS_STRIDE 68
#define VS_STRIDE 40
#define PS_STRIDE 68
#define ATTN_SMEM ((64*KS_STRIDE + 64*VS_STRIDE + 8*16*PS_STRIDE) * 4)

__global__ void __launch_bounds__(256)
attn_tc(const float* __restrict__ qm, const float* __restrict__ km,
        const float* __restrict__ vm, float* __restrict__ sa) {
    extern __shared__ float dynsm[];
    float (*Ks)[KS_STRIDE] = (float (*)[KS_STRIDE])dynsm;
    float (*Vs)[VS_STRIDE] = (float (*)[VS_STRIDE])(dynsm + 64 * KS_STRIDE);
    float (*Ps)[16][PS_STRIDE] =
        (float (*)[16][PS_STRIDE])(dynsm + 64 * KS_STRIDE + 64 * VS_STRIDE);

    const int bh = blockIdx.y;
    const int b = bh >> 3, h = bh & 7;
    const int t = threadIdx.x;
    const int w = t >> 5, lane = t & 31;
    const int l4 = lane & 3, l2 = lane >> 2;
    const int qbase = blockIdx.x * 128 + w * 16;
    const float sc = 0.17677669529663687f;

    uint32_t aq[4][4];
    {
        int r0 = min(qbase + l2,     NQ - 1);
        int r1 = min(qbase + l2 + 8, NQ - 1);
        const float* q0 = qm + ((long)(b * NQ + r0)) * 512 + h * HDD;
        const float* q1 = qm + ((long)(b * NQ + r1)) * 512 + h * HDD;
        #pragma unroll
        for (int ks = 0; ks < 4; ks++) {
            int c = ks * 8 + l4;
            aq[ks][0] = __float_as_uint(to_tf32(q0[c]));
            aq[ks][1] = __float_as_uint(to_tf32(q1[c]));
            aq[ks][2] = __float_as_uint(to_tf32(q0[c + 4]));
            aq[ks][3] = __float_as_uint(to_tf32(q1[c + 4]));
        }
    }

    float m0 = -1e30f, m1 = -1e30f, l0 = 0.f, l1 = 0.f;
    float O[4][4];
    #pragma unroll
    for (int i = 0; i < 4; i++)
        #pragma unroll
        for (int r = 0; r < 4; r++) O[i][r] = 0.f;

    for (int kc = 0; kc < NQ; kc += 64) {
        __syncthreads();
        #pragma unroll
        for (int i = 0; i < 2; i++) {
            int e = t + i * 256;
            int row = e >> 3, c4 = (e & 7) * 4;
            int jg = min(kc + row, NQ - 1);
            float4 kv = *(const float4*)(km + ((long)(b * NQ + jg)) * 512 + h * HDD + c4);
            float4 vv = *(const float4*)(vm + ((long)(b * NQ + jg)) * DD  + h * HDD + c4);
            float4 kt, vt;
            kt.x = to_tf32(kv.x); kt.y = to_tf32(kv.y);
            kt.z = to_tf32(kv.z); kt.w = to_tf32(kv.w);
            vt.x = to_tf32(vv.x); vt.y = to_tf32(vv.y);
            vt.z = to_tf32(vv.z); vt.w = to_tf32(vv.w);
            *(float4*)&Ks[row][c4] = kt;
            *(float4*)&Vs[row][c4] = vt;
        }
        __syncthreads();

        float s[8][4];
        #pragma unroll
        for (int nt = 0; nt < 8; nt++) {
            #pragma unroll
            for (int r = 0; r < 4; r++) s[nt][r] = 0.f;
            #pragma unroll
            for (int ks = 0; ks < 4; ks++) {
                int d = ks * 8 + l4;
                uint32_t b0 = __float_as_uint(Ks[nt * 8 + l2][d]);
                uint32_t b1 = __float_as_uint(Ks[nt * 8 + l2][d + 4]);
                mma_tf32(s[nt], aq[ks][0], aq[ks][1], aq[ks][2], aq[ks][3], b0, b1);
            }
        }

        const int jmax = NQ - kc;
        if (jmax >= 64) {
            #pragma unroll
            for (int nt = 0; nt < 8; nt++)
                #pragma unroll
                for (int r = 0; r < 4; r++) s[nt][r] *= sc;
        } else {
            #pragma unroll
            for (int nt = 0; nt < 8; nt++)
                #pragma unroll
                for (int r = 0; r < 4; r++) {
                    int col = nt * 8 + 2 * l4 + (r & 1);
                    s[nt][r] = (col < jmax) ? s[nt][r] * sc : -1e30f;
                }
        }

        float mx0 = -1e30f, mx1 = -1e30f;
        #pragma unroll
        for (int nt = 0; nt < 8; nt++) {
            mx0 = fmaxf(mx0, fmaxf(s[nt][0], s[nt][1]));
            mx1 = fmaxf(mx1, fmaxf(s[nt][2], s[nt][3]));
        }
        mx0 = fmaxf(mx0, __shfl_xor_sync(0xffffffffu, mx0, 1));
        mx0 = fmaxf(mx0, __shfl_xor_sync(0xffffffffu, mx0, 2));
        mx1 = fmaxf(mx1, __shfl_xor_sync(0xffffffffu, mx1, 1));
        mx1 = fmaxf(mx1, __shfl_xor_sync(0xffffffffu, mx1, 2));

        float nm0 = fmaxf(m0, mx0), nm1 = fmaxf(m1, mx1);
        float cor0 = __expf(m0 - nm0), cor1 = __expf(m1 - nm1);
        m0 = nm0; m1 = nm1;

        float rs0 = 0.f, rs1 = 0.f;
        #pragma unroll
        for (int nt = 0; nt < 8; nt++) {
            float p0 = __expf(s[nt][0] - nm0);
            float p1 = __expf(s[nt][1] - nm0);
            float p2 = __expf(s[nt][2] - nm1);
            float p3 = __expf(s[nt][3] - nm1);
            rs0 += p0 + p1;
            rs1 += p2 + p3;
            int colb = nt * 8 + 2 * l4;
            *(float2*)&Ps[w][l2    ][colb] = make_float2(p0, p1);
            *(float2*)&Ps[w][l2 + 8][colb] = make_float2(p2, p3);
        }
        rs0 += __shfl_xor_sync(0xffffffffu, rs0, 1);
        rs0 += __shfl_xor_sync(0xffffffffu, rs0, 2);
        rs1 += __shfl_xor_sync(0xffffffffu, rs1, 1);
        rs1 += __shfl_xor_sync(0xffffffffu, rs1, 2);
        l0 = l0 * cor0 + rs0;
        l1 = l1 * cor1 + rs1;

        #pragma unroll
        for (int i = 0; i < 4; i++) {
            O[i][0] *= cor0; O[i][1] *= cor0;
            O[i][2] *= cor1; O[i][3] *= cor1;
        }
        __syncwarp();

        #pragma unroll
        for (int ks2 = 0; ks2 < 8; ks2++) {
            int colb = ks2 * 8 + l4;
            uint32_t a0 = __float_as_uint(Ps[w][l2    ][colb]);
            uint32_t a1 = __float_as_uint(Ps[w][l2 + 8][colb]);
            uint32_t a2 = __float_as_uint(Ps[w][l2    ][colb + 4]);
            uint32_t a3 = __float_as_uint(Ps[w][l2 + 8][colb + 4]);
            #pragma unroll
            for (int nt2 = 0; nt2 < 4; nt2++) {
                uint32_t b0 = __float_as_uint(Vs[ks2 * 8 + l4    ][nt2 * 8 + l2]);
                uint32_t b1 = __float_as_uint(Vs[ks2 * 8 + l4 + 4][nt2 * 8 + l2]);
                mma_tf32(O[nt2], a0, a1, a2, a3, b0, b1);
            }
        }
    }

    float inv0 = 1.f / l0, inv1 = 1.f / l1;
    int q0 = qbase + l2, q1 = qbase + l2 + 8;
    if (q0 < NQ) {
        float* o0 = sa + ((long)(b * NQ + q0)) * DD + h * HDD;
        #pragma unroll
        for (int nt2 = 0; nt2 < 4; nt2++)
            *(float2*)(o0 + nt2 * 8 + 2 * l4) = make_float2(O[nt2][0] * inv0, O[nt2][1] * inv0);
    }
    if (q1 < NQ) {
        float* o1 = sa + ((long)(b * NQ + q1)) * DD + h * HDD;
        #pragma unroll
        for (int nt2 = 0; nt2 < 4; nt2++)
            *(float2*)(o1 + nt2 * 8 + 2 * l4) = make_float2(O[nt2][2] * inv1, O[nt2][3] * inv1);
    }
}

// ---------------- fused residual + LayerNorm ----------------
__global__ void ln_k(const float* __restrict__ resid, const float* __restrict__ add,
                     const float* __restrict__ g, const float* __restrict__ bta,
                     float* __restrict__ out) {
    const int r = blockIdx.x, tdx = threadIdx.x;
    const int wid = tdx >> 5, lane = tdx & 31;
    __shared__ float red[8];
    __shared__ float s_mean, s_rstd;

    float x = resid[(long)r * DD + tdx] + add[(long)r * DD + tdx];

    float s = x;
    #pragma unroll
    for (int o = 16; o; o >>= 1) s += __shfl_xor_sync(0xffffffffu, s, o);
    if (lane == 0) red[wid] = s;
    __syncthreads();
    if (tdx == 0) {
        float tot = 0.f;
        #pragma unroll
        for (int i = 0; i < 8; i++) tot += red[i];
        s_mean = tot * (1.f / DD);
    }
    __syncthreads();
    float mean = s_mean;
    float dx = x - mean;

    float s2 = dx * dx;
    #pragma unroll
    for (int o = 16; o; o >>= 1) s2 += __shfl_xor_sync(0xffffffffu, s2, o);
    if (lane == 0) red[wid] = s2;
    __syncthreads();
    if (tdx == 0) {
        float tot = 0.f;
        #pragma unroll
        for (int i = 0; i < 8; i++) tot += red[i];
        s_rstd = rsqrtf(tot * (1.f / DD) + 1e-5f);
    }
    __syncthreads();
    out[(long)r * DD + tdx] = dx * s_rstd * g[tdx] + bta[tdx];
}

// ---------------- attention-weight softmax over 16 ----------------
__global__ void awsm_k(float* __restrict__ aw) {
    int idx = blockIdx.x * 256 + threadIdx.x;
    if (idx >= BNQ * HH) return;
    int bq = idx >> 3, h = idx & 7;
    float* p = aw + (long)bq * 128 + h * 16;
    float m = -1e30f;
    float e[16];
    #pragma unroll
    for (int i = 0; i < 16; i++) m = fmaxf(m, p[i]);
    float sum = 0.f;
    #pragma unroll
    for (int i = 0; i < 16; i++) { e[i] = __expf(p[i] - m); sum += e[i]; }
    float inv = 1.f / sum;
    #pragma unroll
    for (int i = 0; i < 16; i++) p[i] = e[i] * inv;
}

// ---------------- deformable bilinear sampling ----------------
__global__ void samp_k(const float* __restrict__ off, const float* __restrict__ aw,
                       const float* __restrict__ refp, const float* __restrict__ val,
                       float* __restrict__ acc) {
    const int widx = blockIdx.x * 8 + (threadIdx.x >> 5);
    const int lane = threadIdx.x & 31;
    if (widx >= BNQ * HH) return;
    const int b = widx / (NQ * HH);
    const int rem = widx % (NQ * HH);
    const int qI = rem / HH, h = rem % HH;

    const int dims[4]   = {128, 64, 32, 16};
    const int starts[4] = {0, 16384, 20480, 21504};

    const long obase = ((long)(b * NQ + qI)) * DD + h * HDD;
    const long abase = ((long)(b * NQ + qI)) * 128 + h * 16;
    const long vbase = (long)b * SS;

    float a = 0.f;
    #pragma unroll
    for (int l = 0; l < 4; l++) {
        const int Wl = dims[l], Hl = dims[l], st = starts[l];
        float rx = refp[(((long)(b * NQ + qI)) * LL + l) * 2 + 0];
        float ry = refp[(((long)(b * NQ + qI)) * LL + l) * 2 + 1];
        #pragma unroll
        for (int p = 0; p < 4; p++) {
            float x = rx * Wl + off[obase + l * 8 + p * 2 + 0] - 0.5f;
            float y = ry * Hl + off[obase + l * 8 + p * 2 + 1] - 0.5f;
            float x0f = floorf(x), y0f = floorf(y);
            int x0 = (int)x0f, y0 = (int)y0f;
            float wx = x - x0f, wy = y - y0f;
            float w = aw[abase + l * 4 + p];

            float cw[4] = {(1.f - wx) * (1.f - wy), wx * (1.f - wy),
                           (1.f - wx) * wy,          wx * wy};
            int xs[4] = {x0, x0 + 1, x0,     x0 + 1};
            int ys[4] = {y0, y0,     y0 + 1, y0 + 1};
            #pragma unroll
            for (int c = 0; c < 4; c++) {
                int xi = xs[c], yi = ys[c];
                if (xi >= 0 && xi < Wl && yi >= 0 && yi < Hl) {
                    a += w * cw[c] *
                         val[((vbase + st + (long)yi * Wl + xi)) * DD + h * HDD + lane];
                }
            }
        }
    }
    acc[obase + lane] = a;
}

// ---------------- host launch ----------------
static inline void launch_gemm(cudaStream_t st,
                               const float* A, const float* A2, int lda,
                               const float* W, int ldw,
                               const float* bias, float* C, int ldc,
                               int M, int N, int K,
                               int relu, const unsigned char* mask) {
    dim3 grid(N / BN, (M + BM - 1) / BM);
    if (mask)
        gemm_tc<0, 1, 0><<<grid, 128, 0, st>>>(A, nullptr, lda, W, ldw, bias, C, ldc, M, N, K, mask);
    else if (relu)
        gemm_tc<1, 0, 0><<<grid, 128, 0, st>>>(A, nullptr, lda, W, ldw, bias, C, ldc, M, N, K, nullptr);
    else if (A2)
        gemm_tc<0, 0, 1><<<grid, 128, 0, st>>>(A, A2, lda, W, ldw, bias, C, ldc, M, N, K, nullptr);
    else
        gemm_tc<0, 0, 0><<<grid, 128, 0, st>>>(A, nullptr, lda, W, ldw, bias, C, ldc, M, N, K, nullptr);
}

extern "C" void kernel_launch(void* const* d_in, const int* in_sizes, int n_in,
                              void* d_out, int out_size) {
    const float* tgt        = (const float*)d_in[0];
    const float* query_pos  = (const float*)d_in[1];
    const float* refp       = (const float*)d_in[2];
    const float* memory     = (const float*)d_in[3];
    const float* in_proj_w  = (const float*)d_in[4];
    const float* in_proj_b  = (const float*)d_in[5];
    const float* out_proj_w = (const float*)d_in[6];
    const float* out_proj_b = (const float*)d_in[7];
    const float* ln1_g      = (const float*)d_in[8];
    const float* ln1_b      = (const float*)d_in[9];
    const float* ln2_g      = (const float*)d_in[10];
    const float* ln2_b      = (const float*)d_in[11];
    const float* ln3_g      = (const float*)d_in[12];
    const float* ln3_b      = (const float*)d_in[13];
    const float* vproj_w    = (const float*)d_in[14];
    const float* vproj_b    = (const float*)d_in[15];
    const float* off_w      = (const float*)d_in[16];
    const float* off_b      = (const float*)d_in[17];
    const float* aw_w       = (const float*)d_in[18];
    const float* aw_b       = (const float*)d_in[19];
    const float* oproj_w    = (const float*)d_in[20];
    const float* oproj_b    = (const float*)d_in[21];
    const float* lin1_w     = (const float*)d_in[22];
    const float* lin1_b     = (const float*)d_in[23];
    const float* lin2_w     = (const float*)d_in[24];
    const float* lin2_b     = (const float*)d_in[25];
    const unsigned char* mem_mask = (const unsigned char*)d_in[27];
    float* out = (float*)d_out;

    float *qk, *v, *sa, *tmp, *t1, *t2, *offb, *accb, *awb, *valb, *ffh;
    cudaGetSymbolAddress((void**)&qk,  g_qk);
    cudaGetSymbolAddress((void**)&v,   g_v);
    cudaGetSymbolAddress((void**)&sa,  g_sa);
    cudaGetSymbolAddress((void**)&tmp, g_tmp);
    cudaGetSymbolAddress((void**)&t1,  g_t1);
    cudaGetSymbolAddress((void**)&t2,  g_t2);
    cudaGetSymbolAddress((void**)&offb, g_off);
    cudaGetSymbolAddress((void**)&accb, g_acc);
    cudaGetSymbolAddress((void**)&awb,  g_aw);
    cudaGetSymbolAddress((void**)&valb, g_val);
    cudaGetSymbolAddress((void**)&ffh,  g_ffh);

    static int inited = 0;
    static cudaStream_t s2, s3;
    static cudaEvent_t evFork, evV, evVal, evAw;
    if (!inited) {
        cudaFuncSetAttribute(attn_tc, cudaFuncAttributeMaxDynamicSharedMemorySize,
                             ATTN_SMEM);
        cudaStreamCreateWithFlags(&s2, cudaStreamNonBlocking);
        cudaStreamCreateWithFlags(&s3, cudaStreamNonBlocking);
        cudaEventCreateWithFlags(&evFork, cudaEventDisableTiming);
        cudaEventCreateWithFlags(&evV,    cudaEventDisableTiming);
        cudaEventCreateWithFlags(&evVal,  cudaEventDisableTiming);
        cudaEventCreateWithFlags(&evAw,   cudaEventDisableTiming);
        inited = 1;
    }

    cudaStream_t s0 = 0;

    // fork s2
    cudaEventRecord(evFork, s0);
    cudaStreamWaitEvent(s2, evFork, 0);

    // s0: fused q|k projection (A = tgt + query_pos)
    launch_gemm(s0, tgt, query_pos, DD, in_proj_w, 3 * DD, in_proj_b, qk, 512, BNQ, 512, DD, 0, nullptr);

    // s2: v projection, then big value projection
    launch_gemm(s2, tgt, nullptr, DD, in_proj_w + 2 * DD, 3 * DD, in_proj_b + 2 * DD, v, DD, BNQ, DD, DD, 0, nullptr);
    cudaEventRecord(evV, s2);
    launch_gemm(s2, memory, nullptr, DD, vproj_w, DD, vproj_b, valb, DD, BB * SS, DD, DD, 0, mem_mask);
    cudaEventRecord(evVal, s2);

    // s0: attention
    cudaStreamWaitEvent(s0, evV, 0);
    attn_tc<<<dim3((NQ + 127) / 128, BB * HH), 256, ATTN_SMEM, s0>>>(qk, qk + 256, v, sa);

    // s0: out_proj + LN2
    launch_gemm(s0, sa, nullptr, DD, out_proj_w, DD, out_proj_b, tmp, DD, BNQ, DD, DD, 0, nullptr);
    ln_k<<<BNQ, DD, 0, s0>>>(tgt, tmp, ln2_g, ln2_b, t1);

    // fork s3: aw gemm + softmax
    cudaEventRecord(evFork, s0);
    cudaStreamWaitEvent(s3, evFork, 0);
    launch_gemm(s3, t1, query_pos, DD, aw_w, 128, aw_b, awb, 128, BNQ, 128, DD, 0, nullptr);
    awsm_k<<<(BNQ * HH + 255) / 256, 256, 0, s3>>>(awb);
    cudaEventRecord(evAw, s3);

    // s0: off gemm
    launch_gemm(s0, t1, query_pos, DD, off_w, DD, off_b, offb, DD, BNQ, DD, DD, 0, nullptr);

    // s0: sampling
    cudaStreamWaitEvent(s0, evAw, 0);
    cudaStreamWaitEvent(s0, evVal, 0);
    samp_k<<<(BNQ * HH) / 8, 256, 0, s0>>>(offb, awb, refp, valb, accb);

    // s0: output projection + LN1
    launch_gemm(s0, accb, nullptr, DD, oproj_w, DD, oproj_b, tmp, DD, BNQ, DD, DD, 0, nullptr);
    ln_k<<<BNQ, DD, 0, s0>>>(t1, tmp, ln1_g, ln1_b, t2);

    // s0: FFN + LN3
    launch_gemm(s0, t2,  nullptr, DD,  lin1_w, DFF, lin1_b, ffh, DFF, BNQ, DFF, DD, 1, nullptr);
    launch_gemm(s0, ffh, nullptr, DFF, lin2_w, DD,  lin2_b, tmp, DD,  BNQ, DD, DFF, 0, nullptr);
    ln_k<<<BNQ, DD, 0, s0>>>(t2, tmp, ln3_g, ln3_b, out);
}

// round 15
// speedup vs baseline: 1.2000x; 1.2000x over previous
#include <cuda_runtime.h>
#include <math.h>
#include <stdint.h>

// ---------------- problem constants ----------------
#define BB   4
#define NQ   900
#define DD   256
#define HH   8
#define HDD  32
#define LL   4
#define PP   4
#define SS   21760          // 128^2+64^2+32^2+16^2
#define DFF  1024
#define BNQ  (BB*NQ)        // 3600

// ---------------- device scratch ----------------
__device__ float g_qk [BNQ*512];
__device__ float g_v  [BNQ*DD];
__device__ float g_sa [BNQ*DD];
__device__ float g_tmp[BNQ*DD];
__device__ float g_t1 [BNQ*DD];
__device__ float g_t2 [BNQ*DD];
__device__ float g_off[BNQ*DD];
__device__ float g_acc[BNQ*DD];
__device__ float g_aw [BNQ*128];
__device__ float g_val[(long)BB*SS*DD];
__device__ float g_ffh[BNQ*DFF];

// ---------------- tf32 helpers ----------------
__device__ __forceinline__ float to_tf32(float x) {
    uint32_t o;
    asm("cvt.rna.tf32.f32 %0, %1;" : "=r"(o) : "f"(x));
    return __uint_as_float(o);
}

__device__ __forceinline__ void mma_tf32(float c[4],
                                         uint32_t a0, uint32_t a1, uint32_t a2, uint32_t a3,
                                         uint32_t b0, uint32_t b1) {
    asm volatile(
        "mma.sync.aligned.m16n8k8.row.col.f32.tf32.tf32.f32 "
        "{%0,%1,%2,%3}, {%4,%5,%6,%7}, {%8,%9}, {%0,%1,%2,%3};\n"
        : "+f"(c[0]), "+f"(c[1]), "+f"(c[2]), "+f"(c[3])
        : "r"(a0), "r"(a1), "r"(a2), "r"(a3), "r"(b0), "r"(b1));
}

// ---------------- TF32 GEMM: R12-proven (8 warps, 32x64 warp tiles, dbl-buffered) ----------------
#define BM 128
#define BN 128
#define BKg 16
#define LDS_P 136   // ==8 mod 32 -> conflict-free fragment reads

template<int RELU, int MASK, int ADDA>
__global__ void __launch_bounds__(256, 2)
gemm_tc(const float* __restrict__ A, const float* __restrict__ A2, int lda,
        const float* __restrict__ W, int ldw,
        const float* __restrict__ bias,
        float* __restrict__ C, int ldc,
        int M, int N, int K,
        const unsigned char* __restrict__ mask) {
    __shared__ float As[2][BKg][LDS_P];
    __shared__ float Bs[2][BKg][LDS_P];

    const int t    = threadIdx.x;
    const int lane = t & 31;
    const int wid  = t >> 5;
    const int warpM = (wid >> 1) * 32;
    const int warpN = (wid & 1) * 64;
    const int m0b = blockIdx.y * BM;
    const int n0b = blockIdx.x * BN;

    float acc[2][8][4];
    #pragma unroll
    for (int i = 0; i < 2; i++)
        #pragma unroll
        for (int j = 0; j < 8; j++)
            #pragma unroll
            for (int r = 0; r < 4; r++) acc[i][j][r] = 0.f;

    const int arow = t >> 1;
    const int akq  = (t & 1) * 8;
    const int brow = t >> 5;
    const int bcol = (t & 31) * 4;

    float4 ra1, ra2, rb1, rb2;

    auto ldg = [&](int k0) {
        ra1 = make_float4(0.f, 0.f, 0.f, 0.f); ra2 = ra1;
        int gm = m0b + arow;
        if (gm < M) {
            const float* p = A + (long)gm * lda + k0 + akq;
            ra1 = *(const float4*)p;
            ra2 = *(const float4*)(p + 4);
            if (ADDA) {
                const float* p2 = A2 + (long)gm * lda + k0 + akq;
                float4 s1 = *(const float4*)p2;
                float4 s2 = *(const float4*)(p2 + 4);
                ra1.x += s1.x; ra1.y += s1.y; ra1.z += s1.z; ra1.w += s1.w;
                ra2.x += s2.x; ra2.y += s2.y; ra2.z += s2.z; ra2.w += s2.w;
            }
        }
        rb1 = *(const float4*)(W + (long)(k0 + brow    ) * ldw + n0b + bcol);
        rb2 = *(const float4*)(W + (long)(k0 + brow + 8) * ldw + n0b + bcol);
    };

    auto sts = [&](int s) {
        As[s][akq + 0][arow] = to_tf32(ra1.x);
        As[s][akq + 1][arow] = to_tf32(ra1.y);
        As[s][akq + 2][arow] = to_tf32(ra1.z);
        As[s][akq + 3][arow] = to_tf32(ra1.w);
        As[s][akq + 4][arow] = to_tf32(ra2.x);
        As[s][akq + 5][arow] = to_tf32(ra2.y);
        As[s][akq + 6][arow] = to_tf32(ra2.z);
        As[s][akq + 7][arow] = to_tf32(ra2.w);
        float4 g1, g2;
        g1.x = to_tf32(rb1.x); g1.y = to_tf32(rb1.y);
        g1.z = to_tf32(rb1.z); g1.w = to_tf32(rb1.w);
        g2.x = to_tf32(rb2.x); g2.y = to_tf32(rb2.y);
        g2.z = to_tf32(rb2.z); g2.w = to_tf32(rb2.w);
        *(float4*)&Bs[s][brow    ][bcol] = g1;
        *(float4*)&Bs[s][brow + 8][bcol] = g2;
    };

    const int nt = K / BKg;
    ldg(0);
    sts(0);
    if (nt > 1) ldg(BKg);
    __syncthreads();

    int s = 0;
    for (int it = 0; it < nt; it++) {
        #pragma unroll
        for (int ks = 0; ks < 2; ks++) {
            const int kr = ks * 8 + (lane & 3);
            const int mo = warpM + (lane >> 2);
            uint32_t af[2][4];
            #pragma unroll
            for (int i = 0; i < 2; i++) {
                af[i][0] = __float_as_uint(As[s][kr    ][mo + 16 * i    ]);
                af[i][1] = __float_as_uint(As[s][kr    ][mo + 16 * i + 8]);
                af[i][2] = __float_as_uint(As[s][kr + 4][mo + 16 * i    ]);
                af[i][3] = __float_as_uint(As[s][kr + 4][mo + 16 * i + 8]);
            }
            uint32_t bf[8][2];
            const int no = warpN + (lane >> 2);
            #pragma unroll
            for (int j = 0; j < 8; j++) {
                bf[j][0] = __float_as_uint(Bs[s][kr    ][no + 8 * j]);
                bf[j][1] = __float_as_uint(Bs[s][kr + 4][no + 8 * j]);
            }
            #pragma unroll
            for (int i = 0; i < 2; i++)
                #pragma unroll
                for (int j = 0; j < 8; j++)
                    mma_tf32(acc[i][j], af[i][0], af[i][1], af[i][2], af[i][3],
                             bf[j][0], bf[j][1]);
        }
        if (it + 1 < nt) sts(s ^ 1);
        __syncthreads();
        if (it + 2 < nt) ldg((it + 2) * BKg);
        s ^= 1;
    }

    #pragma unroll
    for (int i = 0; i < 2; i++) {
        #pragma unroll
        for (int half = 0; half < 2; half++) {
            int gm = m0b + warpM + 16 * i + (lane >> 2) + half * 8;
            if (gm >= M) continue;
            bool mz = MASK ? (mask[gm] != 0) : false;
            #pragma unroll
            for (int j = 0; j < 8; j++) {
                int gn = n0b + warpN + 8 * j + 2 * (lane & 3);
                float v0 = acc[i][j][half * 2 + 0] + bias[gn];
                float v1 = acc[i][j][half * 2 + 1] + bias[gn + 1];
                if (RELU) { v0 = fmaxf(v0, 0.f); v1 = fmaxf(v1, 0.f); }
                if (mz)   { v0 = 0.f; v1 = 0.f; }
                *(float2*)(C + (long)gm * ldc + gn) = make_float2(v0, v1);
            }
        }
    }
}

// ---------------- tensor-core flash attention (dynamic smem) ----------------
#define KS_STRIDE 68
#define VS_STRIDE 40
#define PS_STRIDE 68
#define ATTN_SMEM ((64*KS_STRIDE + 64*VS_STRIDE + 8*16*PS_STRIDE) * 4)

__global__ void __launch_bounds__(256)
attn_tc(const float* __restrict__ qm, const float* __restrict__ km,
        const float* __restrict__ vm, float* __restrict__ sa) {
    extern __shared__ float dynsm[];
    float (*Ks)[KS_STRIDE] = (float (*)[KS_STRIDE])dynsm;
    float (*Vs)[VS_STRIDE] = (float (*)[VS_STRIDE])(dynsm + 64 * KS_STRIDE);
    float (*Ps)[16][PS_STRIDE] =
        (float (*)[16][PS_STRIDE])(dynsm + 64 * KS_STRIDE + 64 * VS_STRIDE);

    const int bh = blockIdx.y;
    const int b = bh >> 3, h = bh & 7;
    const int t = threadIdx.x;
    const int w = t >> 5, lane = t & 31;
    const int l4 = lane & 3, l2 = lane >> 2;
    const int qbase = blockIdx.x * 128 + w * 16;
    const float sc = 0.17677669529663687f;

    uint32_t aq[4][4];
    {
        int r0 = min(qbase + l2,     NQ - 1);
        int r1 = min(qbase + l2 + 8, NQ - 1);
        const float* q0 = qm + ((long)(b * NQ + r0)) * 512 + h * HDD;
        const float* q1 = qm + ((long)(b * NQ + r1)) * 512 + h * HDD;
        #pragma unroll
        for (int ks = 0; ks < 4; ks++) {
            int c = ks * 8 + l4;
            aq[ks][0] = __float_as_uint(to_tf32(q0[c]));
            aq[ks][1] = __float_as_uint(to_tf32(q1[c]));
            aq[ks][2] = __float_as_uint(to_tf32(q0[c + 4]));
            aq[ks][3] = __float_as_uint(to_tf32(q1[c + 4]));
        }
    }

    float m0 = -1e30f, m1 = -1e30f, l0 = 0.f, l1 = 0.f;
    float O[4][4];
    #pragma unroll
    for (int i = 0; i < 4; i++)
        #pragma unroll
        for (int r = 0; r < 4; r++) O[i][r] = 0.f;

    for (int kc = 0; kc < NQ; kc += 64) {
        __syncthreads();
        #pragma unroll
        for (int i = 0; i < 2; i++) {
            int e = t + i * 256;
            int row = e >> 3, c4 = (e & 7) * 4;
            int jg = min(kc + row, NQ - 1);
            float4 kv = *(const float4*)(km + ((long)(b * NQ + jg)) * 512 + h * HDD + c4);
            float4 vv = *(const float4*)(vm + ((long)(b * NQ + jg)) * DD  + h * HDD + c4);
            float4 kt, vt;
            kt.x = to_tf32(kv.x); kt.y = to_tf32(kv.y);
            kt.z = to_tf32(kv.z); kt.w = to_tf32(kv.w);
            vt.x = to_tf32(vv.x); vt.y = to_tf32(vv.y);
            vt.z = to_tf32(vv.z); vt.w = to_tf32(vv.w);
            *(float4*)&Ks[row][c4] = kt;
            *(float4*)&Vs[row][c4] = vt;
        }
        __syncthreads();

        float s[8][4];
        #pragma unroll
        for (int nt = 0; nt < 8; nt++) {
            #pragma unroll
            for (int r = 0; r < 4; r++) s[nt][r] = 0.f;
            #pragma unroll
            for (int ks = 0; ks < 4; ks++) {
                int d = ks * 8 + l4;
                uint32_t b0 = __float_as_uint(Ks[nt * 8 + l2][d]);
                uint32_t b1 = __float_as_uint(Ks[nt * 8 + l2][d + 4]);
                mma_tf32(s[nt], aq[ks][0], aq[ks][1], aq[ks][2], aq[ks][3], b0, b1);
            }
        }

        const int jmax = NQ - kc;
        if (jmax >= 64) {
            #pragma unroll
            for (int nt = 0; nt < 8; nt++)
                #pragma unroll
                for (int r = 0; r < 4; r++) s[nt][r] *= sc;
        } else {
            #pragma unroll
            for (int nt = 0; nt < 8; nt++)
                #pragma unroll
                for (int r = 0; r < 4; r++) {
                    int col = nt * 8 + 2 * l4 + (r & 1);
                    s[nt][r] = (col < jmax) ? s[nt][r] * sc : -1e30f;
                }
        }

        float mx0 = -1e30f, mx1 = -1e30f;
        #pragma unroll
        for (int nt = 0; nt < 8; nt++) {
            mx0 = fmaxf(mx0, fmaxf(s[nt][0], s[nt][1]));
            mx1 = fmaxf(mx1, fmaxf(s[nt][2], s[nt][3]));
        }
        mx0 = fmaxf(mx0, __shfl_xor_sync(0xffffffffu, mx0, 1));
        mx0 = fmaxf(mx0, __shfl_xor_sync(0xffffffffu, mx0, 2));
        mx1 = fmaxf(mx1, __shfl_xor_sync(0xffffffffu, mx1, 1));
        mx1 = fmaxf(mx1, __shfl_xor_sync(0xffffffffu, mx1, 2));

        float nm0 = fmaxf(m0, mx0), nm1 = fmaxf(m1, mx1);
        float cor0 = __expf(m0 - nm0), cor1 = __expf(m1 - nm1);
        m0 = nm0; m1 = nm1;

        float rs0 = 0.f, rs1 = 0.f;
        #pragma unroll
        for (int nt = 0; nt < 8; nt++) {
            float p0 = __expf(s[nt][0] - nm0);
            float p1 = __expf(s[nt][1] - nm0);
            float p2 = __expf(s[nt][2] - nm1);
            float p3 = __expf(s[nt][3] - nm1);
            rs0 += p0 + p1;
            rs1 += p2 + p3;
            int colb = nt * 8 + 2 * l4;
            *(float2*)&Ps[w][l2    ][colb] = make_float2(p0, p1);
            *(float2*)&Ps[w][l2 + 8][colb] = make_float2(p2, p3);
        }
        rs0 += __shfl_xor_sync(0xffffffffu, rs0, 1);
        rs0 += __shfl_xor_sync(0xffffffffu, rs0, 2);
        rs1 += __shfl_xor_sync(0xffffffffu, rs1, 1);
        rs1 += __shfl_xor_sync(0xffffffffu, rs1, 2);
        l0 = l0 * cor0 + rs0;
        l1 = l1 * cor1 + rs1;

        #pragma unroll
        for (int i = 0; i < 4; i++) {
            O[i][0] *= cor0; O[i][1] *= cor0;
            O[i][2] *= cor1; O[i][3] *= cor1;
        }
        __syncwarp();

        #pragma unroll
        for (int ks2 = 0; ks2 < 8; ks2++) {
            int colb = ks2 * 8 + l4;
            uint32_t a0 = __float_as_uint(Ps[w][l2    ][colb]);
            uint32_t a1 = __float_as_uint(Ps[w][l2 + 8][colb]);
            uint32_t a2 = __float_as_uint(Ps[w][l2    ][colb + 4]);
            uint32_t a3 = __float_as_uint(Ps[w][l2 + 8][colb + 4]);
            #pragma unroll
            for (int nt2 = 0; nt2 < 4; nt2++) {
                uint32_t b0 = __float_as_uint(Vs[ks2 * 8 + l4    ][nt2 * 8 + l2]);
                uint32_t b1 = __float_as_uint(Vs[ks2 * 8 + l4 + 4][nt2 * 8 + l2]);
                mma_tf32(O[nt2], a0, a1, a2, a3, b0, b1);
            }
        }
    }

    float inv0 = 1.f / l0, inv1 = 1.f / l1;
    int q0 = qbase + l2, q1 = qbase + l2 + 8;
    if (q0 < NQ) {
        float* o0 = sa + ((long)(b * NQ + q0)) * DD + h * HDD;
        #pragma unroll
        for (int nt2 = 0; nt2 < 4; nt2++)
            *(float2*)(o0 + nt2 * 8 + 2 * l4) = make_float2(O[nt2][0] * inv0, O[nt2][1] * inv0);
    }
    if (q1 < NQ) {
        float* o1 = sa + ((long)(b * NQ + q1)) * DD + h * HDD;
        #pragma unroll
        for (int nt2 = 0; nt2 < 4; nt2++)
            *(float2*)(o1 + nt2 * 8 + 2 * l4) = make_float2(O[nt2][2] * inv1, O[nt2][3] * inv1);
    }
}

// ---------------- fused residual + LayerNorm ----------------
__global__ void ln_k(const float* __restrict__ resid, const float* __restrict__ add,
                     const float* __restrict__ g, const float* __restrict__ bta,
                     float* __restrict__ out) {
    const int r = blockIdx.x, tdx = threadIdx.x;
    const int wid = tdx >> 5, lane = tdx & 31;
    __shared__ float red[8];
    __shared__ float s_mean, s_rstd;

    float x = resid[(long)r * DD + tdx] + add[(long)r * DD + tdx];

    float s = x;
    #pragma unroll
    for (int o = 16; o; o >>= 1) s += __shfl_xor_sync(0xffffffffu, s, o);
    if (lane == 0) red[wid] = s;
    __syncthreads();
    if (tdx == 0) {
        float tot = 0.f;
        #pragma unroll
        for (int i = 0; i < 8; i++) tot += red[i];
        s_mean = tot * (1.f / DD);
    }
    __syncthreads();
    float mean = s_mean;
    float dx = x - mean;

    float s2 = dx * dx;
    #pragma unroll
    for (int o = 16; o; o >>= 1) s2 += __shfl_xor_sync(0xffffffffu, s2, o);
    if (lane == 0) red[wid] = s2;
    __syncthreads();
    if (tdx == 0) {
        float tot = 0.f;
        #pragma unroll
        for (int i = 0; i < 8; i++) tot += red[i];
        s_rstd = rsqrtf(tot * (1.f / DD) + 1e-5f);
    }
    __syncthreads();
    out[(long)r * DD + tdx] = dx * s_rstd * g[tdx] + bta[tdx];
}

// ---------------- attention-weight softmax over 16 ----------------
__global__ void awsm_k(float* __restrict__ aw) {
    int idx = blockIdx.x * 256 + threadIdx.x;
    if (idx >= BNQ * HH) return;
    int bq = idx >> 3, h = idx & 7;
    float* p = aw + (long)bq * 128 + h * 16;
    float m = -1e30f;
    float e[16];
    #pragma unroll
    for (int i = 0; i < 16; i++) m = fmaxf(m, p[i]);
    float sum = 0.f;
    #pragma unroll
    for (int i = 0; i < 16; i++) { e[i] = __expf(p[i] - m); sum += e[i]; }
    float inv = 1.f / sum;
    #pragma unroll
    for (int i = 0; i < 16; i++) p[i] = e[i] * inv;
}

// ---------------- deformable bilinear sampling: branchless, high-MLP ----------------
__global__ void samp_k(const float* __restrict__ off, const float* __restrict__ aw,
                       const float* __restrict__ refp, const float* __restrict__ val,
                       float* __restrict__ acc) {
    const int widx = blockIdx.x * 8 + (threadIdx.x >> 5);
    const int lane = threadIdx.x & 31;
    if (widx >= BNQ * HH) return;
    const int b = widx / (NQ * HH);
    const int rem = widx % (NQ * HH);
    const int qI = rem / HH, h = rem % HH;

    const int dims[4]   = {128, 64, 32, 16};
    const int starts[4] = {0, 16384, 20480, 21504};

    const long obase = ((long)(b * NQ + qI)) * DD + h * HDD;
    const long abase = ((long)(b * NQ + qI)) * 128 + h * 16;
    const float* vb = val + ((long)b * SS) * DD + h * HDD + lane;

    float a = 0.f;
    #pragma unroll
    for (int l = 0; l < 4; l++) {
        const int Wl = dims[l], st = starts[l];
        const float rx = refp[(((long)(b * NQ + qI)) * LL + l) * 2 + 0];
        const float ry = refp[(((long)(b * NQ + qI)) * LL + l) * 2 + 1];
        #pragma unroll
        for (int p = 0; p < 4; p++) {
            float x = rx * Wl + off[obase + l * 8 + p * 2 + 0] - 0.5f;
            float y = ry * Wl + off[obase + l * 8 + p * 2 + 1] - 0.5f;
            float x0f = floorf(x), y0f = floorf(y);
            int x0 = (int)x0f, y0 = (int)y0f;
            int x1 = x0 + 1,   y1 = y0 + 1;
            float wx = x - x0f, wy = y - y0f;
            float w = aw[abase + l * 4 + p];

            // validity folded into coefficients; indices clamped for safe loads
            float vx0 = (x0 >= 0 && x0 < Wl) ? 1.f : 0.f;
            float vx1 = (x1 >= 0 && x1 < Wl) ? 1.f : 0.f;
            float vy0 = (y0 >= 0 && y0 < Wl) ? 1.f : 0.f;
            float vy1 = (y1 >= 0 && y1 < Wl) ? 1.f : 0.f;
            int x0c = min(max(x0, 0), Wl - 1);
            int x1c = min(max(x1, 0), Wl - 1);
            int y0c = min(max(y0, 0), Wl - 1);
            int y1c = min(max(y1, 0), Wl - 1);

            float c00 = w * (1.f - wx) * (1.f - wy) * vx0 * vy0;
            float c10 = w * wx * (1.f - wy) * vx1 * vy0;
            float c01 = w * (1.f - wx) * wy * vx0 * vy1;
            float c11 = w * wx * wy * vx1 * vy1;

            const float* base = vb + (long)st * DD;
            float v00 = base[((long)y0c * Wl + x0c) * DD];
            float v10 = base[((long)y0c * Wl + x1c) * DD];
            float v01 = base[((long)y1c * Wl + x0c) * DD];
            float v11 = base[((long)y1c * Wl + x1c) * DD];

            a = fmaf(c00, v00, a);
            a = fmaf(c10, v10, a);
            a = fmaf(c01, v01, a);
            a = fmaf(c11, v11, a);
        }
    }
    acc[obase + lane] = a;
}

// ---------------- host launch ----------------
static inline void launch_gemm(cudaStream_t st,
                               const float* A, const float* A2, int lda,
                               const float* W, int ldw,
                               const float* bias, float* C, int ldc,
                               int M, int N, int K,
                               int relu, const unsigned char* mask) {
    dim3 grid(N / BN, (M + BM - 1) / BM);
    if (mask)
        gemm_tc<0, 1, 0><<<grid, 256, 0, st>>>(A, nullptr, lda, W, ldw, bias, C, ldc, M, N, K, mask);
    else if (relu)
        gemm_tc<1, 0, 0><<<grid, 256, 0, st>>>(A, nullptr, lda, W, ldw, bias, C, ldc, M, N, K, nullptr);
    else if (A2)
        gemm_tc<0, 0, 1><<<grid, 256, 0, st>>>(A, A2, lda, W, ldw, bias, C, ldc, M, N, K, nullptr);
    else
        gemm_tc<0, 0, 0><<<grid, 256, 0, st>>>(A, nullptr, lda, W, ldw, bias, C, ldc, M, N, K, nullptr);
}

extern "C" void kernel_launch(void* const* d_in, const int* in_sizes, int n_in,
                              void* d_out, int out_size) {
    const float* tgt        = (const float*)d_in[0];
    const float* query_pos  = (const float*)d_in[1];
    const float* refp       = (const float*)d_in[2];
    const float* memory     = (const float*)d_in[3];
    const float* in_proj_w  = (const float*)d_in[4];
    const float* in_proj_b  = (const float*)d_in[5];
    const float* out_proj_w = (const float*)d_in[6];
    const float* out_proj_b = (const float*)d_in[7];
    const float* ln1_g      = (const float*)d_in[8];
    const float* ln1_b      = (const float*)d_in[9];
    const float* ln2_g      = (const float*)d_in[10];
    const float* ln2_b      = (const float*)d_in[11];
    const float* ln3_g      = (const float*)d_in[12];
    const float* ln3_b      = (const float*)d_in[13];
    const float* vproj_w    = (const float*)d_in[14];
    const float* vproj_b    = (const float*)d_in[15];
    const float* off_w      = (const float*)d_in[16];
    const float* off_b      = (const float*)d_in[17];
    const float* aw_w       = (const float*)d_in[18];
    const float* aw_b       = (const float*)d_in[19];
    const float* oproj_w    = (const float*)d_in[20];
    const float* oproj_b    = (const float*)d_in[21];
    const float* lin1_w     = (const float*)d_in[22];
    const float* lin1_b     = (const float*)d_in[23];
    const float* lin2_w     = (const float*)d_in[24];
    const float* lin2_b     = (const float*)d_in[25];
    const unsigned char* mem_mask = (const unsigned char*)d_in[27];
    float* out = (float*)d_out;

    float *qk, *v, *sa, *tmp, *t1, *t2, *offb, *accb, *awb, *valb, *ffh;
    cudaGetSymbolAddress((void**)&qk,  g_qk);
    cudaGetSymbolAddress((void**)&v,   g_v);
    cudaGetSymbolAddress((void**)&sa,  g_sa);
    cudaGetSymbolAddress((void**)&tmp, g_tmp);
    cudaGetSymbolAddress((void**)&t1,  g_t1);
    cudaGetSymbolAddress((void**)&t2,  g_t2);
    cudaGetSymbolAddress((void**)&offb, g_off);
    cudaGetSymbolAddress((void**)&accb, g_acc);
    cudaGetSymbolAddress((void**)&awb,  g_aw);
    cudaGetSymbolAddress((void**)&valb, g_val);
    cudaGetSymbolAddress((void**)&ffh,  g_ffh);

    static int inited = 0;
    static cudaStream_t s2, s3;
    static cudaEvent_t evFork, evV, evVal, evAw;
    if (!inited) {
        cudaFuncSetAttribute(attn_tc, cudaFuncAttributeMaxDynamicSharedMemorySize,
                             ATTN_SMEM);
        cudaStreamCreateWithFlags(&s2, cudaStreamNonBlocking);
        cudaStreamCreateWithFlags(&s3, cudaStreamNonBlocking);
        cudaEventCreateWithFlags(&evFork, cudaEventDisableTiming);
        cudaEventCreateWithFlags(&evV,    cudaEventDisableTiming);
        cudaEventCreateWithFlags(&evVal,  cudaEventDisableTiming);
        cudaEventCreateWithFlags(&evAw,   cudaEventDisableTiming);
        inited = 1;
    }

    cudaStream_t s0 = 0;

    // fork s2
    cudaEventRecord(evFork, s0);
    cudaStreamWaitEvent(s2, evFork, 0);

    // s0: fused q|k projection (A = tgt + query_pos)
    launch_gemm(s0, tgt, query_pos, DD, in_proj_w, 3 * DD, in_proj_b, qk, 512, BNQ, 512, DD, 0, nullptr);

    // s2: v projection, then big value projection
    launch_gemm(s2, tgt, nullptr, DD, in_proj_w + 2 * DD, 3 * DD, in_proj_b + 2 * DD, v, DD, BNQ, DD, DD, 0, nullptr);
    cudaEventRecord(evV, s2);
    launch_gemm(s2, memory, nullptr, DD, vproj_w, DD, vproj_b, valb, DD, BB * SS, DD, DD, 0, mem_mask);
    cudaEventRecord(evVal, s2);

    // s0: attention
    cudaStreamWaitEvent(s0, evV, 0);
    attn_tc<<<dim3((NQ + 127) / 128, BB * HH), 256, ATTN_SMEM, s0>>>(qk, qk + 256, v, sa);

    // s0: out_proj + LN2
    launch_gemm(s0, sa, nullptr, DD, out_proj_w, DD, out_proj_b, tmp, DD, BNQ, DD, DD, 0, nullptr);
    ln_k<<<BNQ, DD, 0, s0>>>(tgt, tmp, ln2_g, ln2_b, t1);

    // fork s3: aw gemm + softmax
    cudaEventRecord(evFork, s0);
    cudaStreamWaitEvent(s3, evFork, 0);
    launch_gemm(s3, t1, query_pos, DD, aw_w, 128, aw_b, awb, 128, BNQ, 128, DD, 0, nullptr);
    awsm_k<<<(BNQ * HH + 255) / 256, 256, 0, s3>>>(awb);
    cudaEventRecord(evAw, s3);

    // s0: off gemm
    launch_gemm(s0, t1, query_pos, DD, off_w, DD, off_b, offb, DD, BNQ, DD, DD, 0, nullptr);

    // s0: sampling
    cudaStreamWaitEvent(s0, evAw, 0);
    cudaStreamWaitEvent(s0, evVal, 0);
    samp_k<<<(BNQ * HH) / 8, 256, 0, s0>>>(offb, awb, refp, valb, accb);

    // s0: output projection + LN1
    launch_gemm(s0, accb, nullptr, DD, oproj_w, DD, oproj_b, tmp, DD, BNQ, DD, DD, 0, nullptr);
    ln_k<<<BNQ, DD, 0, s0>>>(t1, tmp, ln1_g, ln1_b, t2);

    // s0: FFN + LN3
    launch_gemm(s0, t2,  nullptr, DD,  lin1_w, DFF, lin1_b, ffh, DFF, BNQ, DFF, DD, 1, nullptr);
    launch_gemm(s0, ffh, nullptr, DFF, lin2_w, DD,  lin2_b, tmp, DD,  BNQ, DD, DFF, 0, nullptr);
    ln_k<<<BNQ, DD, 0, s0>>>(t2, tmp, ln3_g, ln3_b, out);
}

// round 16
// speedup vs baseline: 1.2831x; 1.0693x over previous
#include <cuda_runtime.h>
#include <math.h>
#include <stdint.h>

// ---------------- problem constants ----------------
#define BB   4
#define NQ   900
#define DD   256
#define HH   8
#define HDD  32
#define LL   4
#define PP   4
#define SS   21760          // 128^2+64^2+32^2+16^2
#define DFF  1024
#define BNQ  (BB*NQ)        // 3600
#define KSPL 4              // split-K factor for lin2

// ---------------- device scratch ----------------
__device__ float g_qk [BNQ*512];
__device__ float g_v  [BNQ*DD];
__device__ float g_sa [BNQ*DD];
__device__ float g_tmp[BNQ*DD];
__device__ float g_t1 [BNQ*DD];
__device__ float g_t2 [BNQ*DD];
__device__ float g_off[BNQ*DD];
__device__ float g_acc[BNQ*DD];
__device__ float g_aw [BNQ*128];
__device__ float g_val[(long)BB*SS*DD];
__device__ float g_ffh[BNQ*DFF];
__device__ float g_part[(long)KSPL*BNQ*DD];

// ---------------- tf32 helpers ----------------
__device__ __forceinline__ float to_tf32(float x) {
    uint32_t o;
    asm("cvt.rna.tf32.f32 %0, %1;" : "=r"(o) : "f"(x));
    return __uint_as_float(o);
}

__device__ __forceinline__ void mma_tf32(float c[4],
                                         uint32_t a0, uint32_t a1, uint32_t a2, uint32_t a3,
                                         uint32_t b0, uint32_t b1) {
    asm volatile(
        "mma.sync.aligned.m16n8k8.row.col.f32.tf32.tf32.f32 "
        "{%0,%1,%2,%3}, {%4,%5,%6,%7}, {%8,%9}, {%0,%1,%2,%3};\n"
        : "+f"(c[0]), "+f"(c[1]), "+f"(c[2]), "+f"(c[3])
        : "r"(a0), "r"(a1), "r"(a2), "r"(a3), "r"(b0), "r"(b1));
}

// ---------------- TF32 GEMM (R12-proven) + optional split-K partial mode ----------------
// SPLITK>1: blockIdx.z selects K-slice; writes raw partials (no bias/relu/mask)
// to C + z*M*ldc. K parameter is the PER-SLICE depth.
#define BM 128
#define BN 128
#define BKg 16
#define LDS_P 136   // ==8 mod 32 -> conflict-free fragment reads

template<int RELU, int MASK, int ADDA, int SPLITK>
__global__ void __launch_bounds__(256, 2)
gemm_tc(const float* __restrict__ A, const float* __restrict__ A2, int lda,
        const float* __restrict__ W, int ldw,
        const float* __restrict__ bias,
        float* __restrict__ C, int ldc,
        int M, int N, int K,
        const unsigned char* __restrict__ mask) {
    __shared__ float As[2][BKg][LDS_P];
    __shared__ float Bs[2][BKg][LDS_P];

    if (SPLITK > 1) {
        int z = blockIdx.z;
        A += (long)z * K;
        W += (long)z * K * ldw;
        C += (long)z * M * ldc;
    }

    const int t    = threadIdx.x;
    const int lane = t & 31;
    const int wid  = t >> 5;
    const int warpM = (wid >> 1) * 32;
    const int warpN = (wid & 1) * 64;
    const int m0b = blockIdx.y * BM;
    const int n0b = blockIdx.x * BN;

    float acc[2][8][4];
    #pragma unroll
    for (int i = 0; i < 2; i++)
        #pragma unroll
        for (int j = 0; j < 8; j++)
            #pragma unroll
            for (int r = 0; r < 4; r++) acc[i][j][r] = 0.f;

    const int arow = t >> 1;
    const int akq  = (t & 1) * 8;
    const int brow = t >> 5;
    const int bcol = (t & 31) * 4;

    float4 ra1, ra2, rb1, rb2;

    auto ldg = [&](int k0) {
        ra1 = make_float4(0.f, 0.f, 0.f, 0.f); ra2 = ra1;
        int gm = m0b + arow;
        if (gm < M) {
            const float* p = A + (long)gm * lda + k0 + akq;
            ra1 = *(const float4*)p;
            ra2 = *(const float4*)(p + 4);
            if (ADDA) {
                const float* p2 = A2 + (long)gm * lda + k0 + akq;
                float4 s1 = *(const float4*)p2;
                float4 s2 = *(const float4*)(p2 + 4);
                ra1.x += s1.x; ra1.y += s1.y; ra1.z += s1.z; ra1.w += s1.w;
                ra2.x += s2.x; ra2.y += s2.y; ra2.z += s2.z; ra2.w += s2.w;
            }
        }
        rb1 = *(const float4*)(W + (long)(k0 + brow    ) * ldw + n0b + bcol);
        rb2 = *(const float4*)(W + (long)(k0 + brow + 8) * ldw + n0b + bcol);
    };

    auto sts = [&](int s) {
        As[s][akq + 0][arow] = to_tf32(ra1.x);
        As[s][akq + 1][arow] = to_tf32(ra1.y);
        As[s][akq + 2][arow] = to_tf32(ra1.z);
        As[s][akq + 3][arow] = to_tf32(ra1.w);
        As[s][akq + 4][arow] = to_tf32(ra2.x);
        As[s][akq + 5][arow] = to_tf32(ra2.y);
        As[s][akq + 6][arow] = to_tf32(ra2.z);
        As[s][akq + 7][arow] = to_tf32(ra2.w);
        float4 g1, g2;
        g1.x = to_tf32(rb1.x); g1.y = to_tf32(rb1.y);
        g1.z = to_tf32(rb1.z); g1.w = to_tf32(rb1.w);
        g2.x = to_tf32(rb2.x); g2.y = to_tf32(rb2.y);
        g2.z = to_tf32(rb2.z); g2.w = to_tf32(rb2.w);
        *(float4*)&Bs[s][brow    ][bcol] = g1;
        *(float4*)&Bs[s][brow + 8][bcol] = g2;
    };

    const int nt = K / BKg;
    ldg(0);
    sts(0);
    if (nt > 1) ldg(BKg);
    __syncthreads();

    int s = 0;
    for (int it = 0; it < nt; it++) {
        #pragma unroll
        for (int ks = 0; ks < 2; ks++) {
            const int kr = ks * 8 + (lane & 3);
            const int mo = warpM + (lane >> 2);
            uint32_t af[2][4];
            #pragma unroll
            for (int i = 0; i < 2; i++) {
                af[i][0] = __float_as_uint(As[s][kr    ][mo + 16 * i    ]);
                af[i][1] = __float_as_uint(As[s][kr    ][mo + 16 * i + 8]);
                af[i][2] = __float_as_uint(As[s][kr + 4][mo + 16 * i    ]);
                af[i][3] = __float_as_uint(As[s][kr + 4][mo + 16 * i + 8]);
            }
            uint32_t bf[8][2];
            const int no = warpN + (lane >> 2);
            #pragma unroll
            for (int j = 0; j < 8; j++) {
                bf[j][0] = __float_as_uint(Bs[s][kr    ][no + 8 * j]);
                bf[j][1] = __float_as_uint(Bs[s][kr + 4][no + 8 * j]);
            }
            #pragma unroll
            for (int i = 0; i < 2; i++)
                #pragma unroll
                for (int j = 0; j < 8; j++)
                    mma_tf32(acc[i][j], af[i][0], af[i][1], af[i][2], af[i][3],
                             bf[j][0], bf[j][1]);
        }
        if (it + 1 < nt) sts(s ^ 1);
        __syncthreads();
        if (it + 2 < nt) ldg((it + 2) * BKg);
        s ^= 1;
    }

    #pragma unroll
    for (int i = 0; i < 2; i++) {
        #pragma unroll
        for (int half = 0; half < 2; half++) {
            int gm = m0b + warpM + 16 * i + (lane >> 2) + half * 8;
            if (gm >= M) continue;
            bool mz = MASK ? (mask[gm] != 0) : false;
            #pragma unroll
            for (int j = 0; j < 8; j++) {
                int gn = n0b + warpN + 8 * j + 2 * (lane & 3);
                float v0 = acc[i][j][half * 2 + 0];
                float v1 = acc[i][j][half * 2 + 1];
                if (SPLITK == 1) {
                    v0 += bias[gn];
                    v1 += bias[gn + 1];
                    if (RELU) { v0 = fmaxf(v0, 0.f); v1 = fmaxf(v1, 0.f); }
                    if (mz)   { v0 = 0.f; v1 = 0.f; }
                }
                *(float2*)(C + (long)gm * ldc + gn) = make_float2(v0, v1);
            }
        }
    }
}

// ---------------- tensor-core flash attention (dynamic smem) ----------------
#define KS_STRIDE 68
#define VS_STRIDE 40
#define PS_STRIDE 68
#define ATTN_SMEM ((64*KS_STRIDE + 64*VS_STRIDE + 8*16*PS_STRIDE) * 4)

__global__ void __launch_bounds__(256)
attn_tc(const float* __restrict__ qm, const float* __restrict__ km,
        const float* __restrict__ vm, float* __restrict__ sa) {
    extern __shared__ float dynsm[];
    float (*Ks)[KS_STRIDE] = (float (*)[KS_STRIDE])dynsm;
    float (*Vs)[VS_STRIDE] = (float (*)[VS_STRIDE])(dynsm + 64 * KS_STRIDE);
    float (*Ps)[16][PS_STRIDE] =
        (float (*)[16][PS_STRIDE])(dynsm + 64 * KS_STRIDE + 64 * VS_STRIDE);

    const int bh = blockIdx.y;
    const int b = bh >> 3, h = bh & 7;
    const int t = threadIdx.x;
    const int w = t >> 5, lane = t & 31;
    const int l4 = lane & 3, l2 = lane >> 2;
    const int qbase = blockIdx.x * 128 + w * 16;
    const float sc = 0.17677669529663687f;

    uint32_t aq[4][4];
    {
        int r0 = min(qbase + l2,     NQ - 1);
        int r1 = min(qbase + l2 + 8, NQ - 1);
        const float* q0 = qm + ((long)(b * NQ + r0)) * 512 + h * HDD;
        const float* q1 = qm + ((long)(b * NQ + r1)) * 512 + h * HDD;
        #pragma unroll
        for (int ks = 0; ks < 4; ks++) {
            int c = ks * 8 + l4;
            aq[ks][0] = __float_as_uint(to_tf32(q0[c]));
            aq[ks][1] = __float_as_uint(to_tf32(q1[c]));
            aq[ks][2] = __float_as_uint(to_tf32(q0[c + 4]));
            aq[ks][3] = __float_as_uint(to_tf32(q1[c + 4]));
        }
    }

    float m0 = -1e30f, m1 = -1e30f, l0 = 0.f, l1 = 0.f;
    float O[4][4];
    #pragma unroll
    for (int i = 0; i < 4; i++)
        #pragma unroll
        for (int r = 0; r < 4; r++) O[i][r] = 0.f;

    for (int kc = 0; kc < NQ; kc += 64) {
        __syncthreads();
        #pragma unroll
        for (int i = 0; i < 2; i++) {
            int e = t + i * 256;
            int row = e >> 3, c4 = (e & 7) * 4;
            int jg = min(kc + row, NQ - 1);
            float4 kv = *(const float4*)(km + ((long)(b * NQ + jg)) * 512 + h * HDD + c4);
            float4 vv = *(const float4*)(vm + ((long)(b * NQ + jg)) * DD  + h * HDD + c4);
            float4 kt, vt;
            kt.x = to_tf32(kv.x); kt.y = to_tf32(kv.y);
            kt.z = to_tf32(kv.z); kt.w = to_tf32(kv.w);
            vt.x = to_tf32(vv.x); vt.y = to_tf32(vv.y);
            vt.z = to_tf32(vv.z); vt.w = to_tf32(vv.w);
            *(float4*)&Ks[row][c4] = kt;
            *(float4*)&Vs[row][c4] = vt;
        }
        __syncthreads();

        float s[8][4];
        #pragma unroll
        for (int nt = 0; nt < 8; nt++) {
            #pragma unroll
            for (int r = 0; r < 4; r++) s[nt][r] = 0.f;
            #pragma unroll
            for (int ks = 0; ks < 4; ks++) {
                int d = ks * 8 + l4;
                uint32_t b0 = __float_as_uint(Ks[nt * 8 + l2][d]);
                uint32_t b1 = __float_as_uint(Ks[nt * 8 + l2][d + 4]);
                mma_tf32(s[nt], aq[ks][0], aq[ks][1], aq[ks][2], aq[ks][3], b0, b1);
            }
        }

        const int jmax = NQ - kc;
        if (jmax >= 64) {
            #pragma unroll
            for (int nt = 0; nt < 8; nt++)
                #pragma unroll
                for (int r = 0; r < 4; r++) s[nt][r] *= sc;
        } else {
            #pragma unroll
            for (int nt = 0; nt < 8; nt++)
                #pragma unroll
                for (int r = 0; r < 4; r++) {
                    int col = nt * 8 + 2 * l4 + (r & 1);
                    s[nt][r] = (col < jmax) ? s[nt][r] * sc : -1e30f;
                }
        }

        float mx0 = -1e30f, mx1 = -1e30f;
        #pragma unroll
        for (int nt = 0; nt < 8; nt++) {
            mx0 = fmaxf(mx0, fmaxf(s[nt][0], s[nt][1]));
            mx1 = fmaxf(mx1, fmaxf(s[nt][2], s[nt][3]));
        }
        mx0 = fmaxf(mx0, __shfl_xor_sync(0xffffffffu, mx0, 1));
        mx0 = fmaxf(mx0, __shfl_xor_sync(0xffffffffu, mx0, 2));
        mx1 = fmaxf(mx1, __shfl_xor_sync(0xffffffffu, mx1, 1));
        mx1 = fmaxf(mx1, __shfl_xor_sync(0xffffffffu, mx1, 2));

        float nm0 = fmaxf(m0, mx0), nm1 = fmaxf(m1, mx1);
        float cor0 = __expf(m0 - nm0), cor1 = __expf(m1 - nm1);
        m0 = nm0; m1 = nm1;

        float rs0 = 0.f, rs1 = 0.f;
        #pragma unroll
        for (int nt = 0; nt < 8; nt++) {
            float p0 = __expf(s[nt][0] - nm0);
            float p1 = __expf(s[nt][1] - nm0);
            float p2 = __expf(s[nt][2] - nm1);
            float p3 = __expf(s[nt][3] - nm1);
            rs0 += p0 + p1;
            rs1 += p2 + p3;
            int colb = nt * 8 + 2 * l4;
            *(float2*)&Ps[w][l2    ][colb] = make_float2(p0, p1);
            *(float2*)&Ps[w][l2 + 8][colb] = make_float2(p2, p3);
        }
        rs0 += __shfl_xor_sync(0xffffffffu, rs0, 1);
        rs0 += __shfl_xor_sync(0xffffffffu, rs0, 2);
        rs1 += __shfl_xor_sync(0xffffffffu, rs1, 1);
        rs1 += __shfl_xor_sync(0xffffffffu, rs1, 2);
        l0 = l0 * cor0 + rs0;
        l1 = l1 * cor1 + rs1;

        #pragma unroll
        for (int i = 0; i < 4; i++) {
            O[i][0] *= cor0; O[i][1] *= cor0;
            O[i][2] *= cor1; O[i][3] *= cor1;
        }
        __syncwarp();

        #pragma unroll
        for (int ks2 = 0; ks2 < 8; ks2++) {
            int colb = ks2 * 8 + l4;
            uint32_t a0 = __float_as_uint(Ps[w][l2    ][colb]);
            uint32_t a1 = __float_as_uint(Ps[w][l2 + 8][colb]);
            uint32_t a2 = __float_as_uint(Ps[w][l2    ][colb + 4]);
            uint32_t a3 = __float_as_uint(Ps[w][l2 + 8][colb + 4]);
            #pragma unroll
            for (int nt2 = 0; nt2 < 4; nt2++) {
                uint32_t b0 = __float_as_uint(Vs[ks2 * 8 + l4    ][nt2 * 8 + l2]);
                uint32_t b1 = __float_as_uint(Vs[ks2 * 8 + l4 + 4][nt2 * 8 + l2]);
                mma_tf32(O[nt2], a0, a1, a2, a3, b0, b1);
            }
        }
    }

    float inv0 = 1.f / l0, inv1 = 1.f / l1;
    int q0 = qbase + l2, q1 = qbase + l2 + 8;
    if (q0 < NQ) {
        float* o0 = sa + ((long)(b * NQ + q0)) * DD + h * HDD;
        #pragma unroll
        for (int nt2 = 0; nt2 < 4; nt2++)
            *(float2*)(o0 + nt2 * 8 + 2 * l4) = make_float2(O[nt2][0] * inv0, O[nt2][1] * inv0);
    }
    if (q1 < NQ) {
        float* o1 = sa + ((long)(b * NQ + q1)) * DD + h * HDD;
        #pragma unroll
        for (int nt2 = 0; nt2 < 4; nt2++)
            *(float2*)(o1 + nt2 * 8 + 2 * l4) = make_float2(O[nt2][2] * inv1, O[nt2][3] * inv1);
    }
}

// ---------------- fused residual + LayerNorm ----------------
__global__ void ln_k(const float* __restrict__ resid, const float* __restrict__ add,
                     const float* __restrict__ g, const float* __restrict__ bta,
                     float* __restrict__ out) {
    const int r = blockIdx.x, tdx = threadIdx.x;
    const int wid = tdx >> 5, lane = tdx & 31;
    __shared__ float red[8];
    __shared__ float s_mean, s_rstd;

    float x = resid[(long)r * DD + tdx] + add[(long)r * DD + tdx];

    float s = x;
    #pragma unroll
    for (int o = 16; o; o >>= 1) s += __shfl_xor_sync(0xffffffffu, s, o);
    if (lane == 0) red[wid] = s;
    __syncthreads();
    if (tdx == 0) {
        float tot = 0.f;
        #pragma unroll
        for (int i = 0; i < 8; i++) tot += red[i];
        s_mean = tot * (1.f / DD);
    }
    __syncthreads();
    float mean = s_mean;
    float dx = x - mean;

    float s2 = dx * dx;
    #pragma unroll
    for (int o = 16; o; o >>= 1) s2 += __shfl_xor_sync(0xffffffffu, s2, o);
    if (lane == 0) red[wid] = s2;
    __syncthreads();
    if (tdx == 0) {
        float tot = 0.f;
        #pragma unroll
        for (int i = 0; i < 8; i++) tot += red[i];
        s_rstd = rsqrtf(tot * (1.f / DD) + 1e-5f);
    }
    __syncthreads();
    out[(long)r * DD + tdx] = dx * s_rstd * g[tdx] + bta[tdx];
}

// ---------------- split-K combine + residual + LayerNorm ----------------
__global__ void ln_comb_k(const float* __restrict__ resid,
                          const float* __restrict__ part,
                          const float* __restrict__ bias,
                          const float* __restrict__ g, const float* __restrict__ bta,
                          float* __restrict__ out) {
    const int r = blockIdx.x, tdx = threadIdx.x;
    const int wid = tdx >> 5, lane = tdx & 31;
    __shared__ float red[8];
    __shared__ float s_mean, s_rstd;

    float x = resid[(long)r * DD + tdx] + bias[tdx];
    #pragma unroll
    for (int z = 0; z < KSPL; z++)
        x += part[(long)z * BNQ * DD + (long)r * DD + tdx];

    float s = x;
    #pragma unroll
    for (int o = 16; o; o >>= 1) s += __shfl_xor_sync(0xffffffffu, s, o);
    if (lane == 0) red[wid] = s;
    __syncthreads();
    if (tdx == 0) {
        float tot = 0.f;
        #pragma unroll
        for (int i = 0; i < 8; i++) tot += red[i];
        s_mean = tot * (1.f / DD);
    }
    __syncthreads();
    float mean = s_mean;
    float dx = x - mean;

    float s2 = dx * dx;
    #pragma unroll
    for (int o = 16; o; o >>= 1) s2 += __shfl_xor_sync(0xffffffffu, s2, o);
    if (lane == 0) red[wid] = s2;
    __syncthreads();
    if (tdx == 0) {
        float tot = 0.f;
        #pragma unroll
        for (int i = 0; i < 8; i++) tot += red[i];
        s_rstd = rsqrtf(tot * (1.f / DD) + 1e-5f);
    }
    __syncthreads();
    out[(long)r * DD + tdx] = dx * s_rstd * g[tdx] + bta[tdx];
}

// ---------------- attention-weight softmax over 16 ----------------
__global__ void awsm_k(float* __restrict__ aw) {
    int idx = blockIdx.x * 256 + threadIdx.x;
    if (idx >= BNQ * HH) return;
    int bq = idx >> 3, h = idx & 7;
    float* p = aw + (long)bq * 128 + h * 16;
    float m = -1e30f;
    float e[16];
    #pragma unroll
    for (int i = 0; i < 16; i++) m = fmaxf(m, p[i]);
    float sum = 0.f;
    #pragma unroll
    for (int i = 0; i < 16; i++) { e[i] = __expf(p[i] - m); sum += e[i]; }
    float inv = 1.f / sum;
    #pragma unroll
    for (int i = 0; i < 16; i++) p[i] = e[i] * inv;
}

// ---------------- deformable bilinear sampling: branchless ----------------
__global__ void samp_k(const float* __restrict__ off, const float* __restrict__ aw,
                       const float* __restrict__ refp, const float* __restrict__ val,
                       float* __restrict__ acc) {
    const int widx = blockIdx.x * 8 + (threadIdx.x >> 5);
    const int lane = threadIdx.x & 31;
    if (widx >= BNQ * HH) return;
    const int b = widx / (NQ * HH);
    const int rem = widx % (NQ * HH);
    const int qI = rem / HH, h = rem % HH;

    const int dims[4]   = {128, 64, 32, 16};
    const int starts[4] = {0, 16384, 20480, 21504};

    const long obase = ((long)(b * NQ + qI)) * DD + h * HDD;
    const long abase = ((long)(b * NQ + qI)) * 128 + h * 16;
    const float* vb = val + ((long)b * SS) * DD + h * HDD + lane;

    float a = 0.f;
    #pragma unroll
    for (int l = 0; l < 4; l++) {
        const int Wl = dims[l], st = starts[l];
        const float rx = refp[(((long)(b * NQ + qI)) * LL + l) * 2 + 0];
        const float ry = refp[(((long)(b * NQ + qI)) * LL + l) * 2 + 1];
        #pragma unroll
        for (int p = 0; p < 4; p++) {
            float x = rx * Wl + off[obase + l * 8 + p * 2 + 0] - 0.5f;
            float y = ry * Wl + off[obase + l * 8 + p * 2 + 1] - 0.5f;
            float x0f = floorf(x), y0f = floorf(y);
            int x0 = (int)x0f, y0 = (int)y0f;
            int x1 = x0 + 1,   y1 = y0 + 1;
            float wx = x - x0f, wy = y - y0f;
            float w = aw[abase + l * 4 + p];

            float vx0 = (x0 >= 0 && x0 < Wl) ? 1.f : 0.f;
            float vx1 = (x1 >= 0 && x1 < Wl) ? 1.f : 0.f;
            float vy0 = (y0 >= 0 && y0 < Wl) ? 1.f : 0.f;
            float vy1 = (y1 >= 0 && y1 < Wl) ? 1.f : 0.f;
            int x0c = min(max(x0, 0), Wl - 1);
            int x1c = min(max(x1, 0), Wl - 1);
            int y0c = min(max(y0, 0), Wl - 1);
            int y1c = min(max(y1, 0), Wl - 1);

            float c00 = w * (1.f - wx) * (1.f - wy) * vx0 * vy0;
            float c10 = w * wx * (1.f - wy) * vx1 * vy0;
            float c01 = w * (1.f - wx) * wy * vx0 * vy1;
            float c11 = w * wx * wy * vx1 * vy1;

            const float* base = vb + (long)st * DD;
            float v00 = base[((long)y0c * Wl + x0c) * DD];
            float v10 = base[((long)y0c * Wl + x1c) * DD];
            float v01 = base[((long)y1c * Wl + x0c) * DD];
            float v11 = base[((long)y1c * Wl + x1c) * DD];

            a = fmaf(c00, v00, a);
            a = fmaf(c10, v10, a);
            a = fmaf(c01, v01, a);
            a = fmaf(c11, v11, a);
        }
    }
    acc[obase + lane] = a;
}

// ---------------- host launch ----------------
static inline void launch_gemm(cudaStream_t st,
                               const float* A, const float* A2, int lda,
                               const float* W, int ldw,
                               const float* bias, float* C, int ldc,
                               int M, int N, int K,
                               int relu, const unsigned char* mask) {
    dim3 grid(N / BN, (M + BM - 1) / BM);
    if (mask)
        gemm_tc<0, 1, 0, 1><<<grid, 256, 0, st>>>(A, nullptr, lda, W, ldw, bias, C, ldc, M, N, K, mask);
    else if (relu)
        gemm_tc<1, 0, 0, 1><<<grid, 256, 0, st>>>(A, nullptr, lda, W, ldw, bias, C, ldc, M, N, K, nullptr);
    else if (A2)
        gemm_tc<0, 0, 1, 1><<<grid, 256, 0, st>>>(A, A2, lda, W, ldw, bias, C, ldc, M, N, K, nullptr);
    else
        gemm_tc<0, 0, 0, 1><<<grid, 256, 0, st>>>(A, nullptr, lda, W, ldw, bias, C, ldc, M, N, K, nullptr);
}

extern "C" void kernel_launch(void* const* d_in, const int* in_sizes, int n_in,
                              void* d_out, int out_size) {
    const float* tgt        = (const float*)d_in[0];
    const float* query_pos  = (const float*)d_in[1];
    const float* refp       = (const float*)d_in[2];
    const float* memory     = (const float*)d_in[3];
    const float* in_proj_w  = (const float*)d_in[4];
    const float* in_proj_b  = (const float*)d_in[5];
    const float* out_proj_w = (const float*)d_in[6];
    const float* out_proj_b = (const float*)d_in[7];
    const float* ln1_g      = (const float*)d_in[8];
    const float* ln1_b      = (const float*)d_in[9];
    const float* ln2_g      = (const float*)d_in[10];
    const float* ln2_b      = (const float*)d_in[11];
    const float* ln3_g      = (const float*)d_in[12];
    const float* ln3_b      = (const float*)d_in[13];
    const float* vproj_w    = (const float*)d_in[14];
    const float* vproj_b    = (const float*)d_in[15];
    const float* off_w      = (const float*)d_in[16];
    const float* off_b      = (const float*)d_in[17];
    const float* aw_w       = (const float*)d_in[18];
    const float* aw_b       = (const float*)d_in[19];
    const float* oproj_w    = (const float*)d_in[20];
    const float* oproj_b    = (const float*)d_in[21];
    const float* lin1_w     = (const float*)d_in[22];
    const float* lin1_b     = (const float*)d_in[23];
    const float* lin2_w     = (const float*)d_in[24];
    const float* lin2_b     = (const float*)d_in[25];
    const unsigned char* mem_mask = (const unsigned char*)d_in[27];
    float* out = (float*)d_out;

    float *qk, *v, *sa, *tmp, *t1, *t2, *offb, *accb, *awb, *valb, *ffh, *partb;
    cudaGetSymbolAddress((void**)&qk,  g_qk);
    cudaGetSymbolAddress((void**)&v,   g_v);
    cudaGetSymbolAddress((void**)&sa,  g_sa);
    cudaGetSymbolAddress((void**)&tmp, g_tmp);
    cudaGetSymbolAddress((void**)&t1,  g_t1);
    cudaGetSymbolAddress((void**)&t2,  g_t2);
    cudaGetSymbolAddress((void**)&offb, g_off);
    cudaGetSymbolAddress((void**)&accb, g_acc);
    cudaGetSymbolAddress((void**)&awb,  g_aw);
    cudaGetSymbolAddress((void**)&valb, g_val);
    cudaGetSymbolAddress((void**)&ffh,  g_ffh);
    cudaGetSymbolAddress((void**)&partb, g_part);

    static int inited = 0;
    static cudaStream_t s2, s3;
    static cudaEvent_t evFork, evV, evVal, evAw;
    if (!inited) {
        cudaFuncSetAttribute(attn_tc, cudaFuncAttributeMaxDynamicSharedMemorySize,
                             ATTN_SMEM);
        cudaStreamCreateWithFlags(&s2, cudaStreamNonBlocking);
        cudaStreamCreateWithFlags(&s3, cudaStreamNonBlocking);
        cudaEventCreateWithFlags(&evFork, cudaEventDisableTiming);
        cudaEventCreateWithFlags(&evV,    cudaEventDisableTiming);
        cudaEventCreateWithFlags(&evVal,  cudaEventDisableTiming);
        cudaEventCreateWithFlags(&evAw,   cudaEventDisableTiming);
        inited = 1;
    }

    cudaStream_t s0 = 0;

    // fork s2
    cudaEventRecord(evFork, s0);
    cudaStreamWaitEvent(s2, evFork, 0);

    // s0: fused q|k projection (A = tgt + query_pos)
    launch_gemm(s0, tgt, query_pos, DD, in_proj_w, 3 * DD, in_proj_b, qk, 512, BNQ, 512, DD, 0, nullptr);

    // s2: v projection, then big value projection
    launch_gemm(s2, tgt, nullptr, DD, in_proj_w + 2 * DD, 3 * DD, in_proj_b + 2 * DD, v, DD, BNQ, DD, DD, 0, nullptr);
    cudaEventRecord(evV, s2);
    launch_gemm(s2, memory, nullptr, DD, vproj_w, DD, vproj_b, valb, DD, BB * SS, DD, DD, 0, mem_mask);
    cudaEventRecord(evVal, s2);

    // s0: attention
    cudaStreamWaitEvent(s0, evV, 0);
    attn_tc<<<dim3((NQ + 127) / 128, BB * HH), 256, ATTN_SMEM, s0>>>(qk, qk + 256, v, sa);

    // s0: out_proj + LN2
    launch_gemm(s0, sa, nullptr, DD, out_proj_w, DD, out_proj_b, tmp, DD, BNQ, DD, DD, 0, nullptr);
    ln_k<<<BNQ, DD, 0, s0>>>(tgt, tmp, ln2_g, ln2_b, t1);

    // fork s3: aw gemm + softmax
    cudaEventRecord(evFork, s0);
    cudaStreamWaitEvent(s3, evFork, 0);
    launch_gemm(s3, t1, query_pos, DD, aw_w, 128, aw_b, awb, 128, BNQ, 128, DD, 0, nullptr);
    awsm_k<<<(BNQ * HH + 255) / 256, 256, 0, s3>>>(awb);
    cudaEventRecord(evAw, s3);

    // s0: off gemm
    launch_gemm(s0, t1, query_pos, DD, off_w, DD, off_b, offb, DD, BNQ, DD, DD, 0, nullptr);

    // s0: sampling
    cudaStreamWaitEvent(s0, evAw, 0);
    cudaStreamWaitEvent(s0, evVal, 0);
    samp_k<<<(BNQ * HH) / 8, 256, 0, s0>>>(offb, awb, refp, valb, accb);

    // s0: output projection + LN1
    launch_gemm(s0, accb, nullptr, DD, oproj_w, DD, oproj_b, tmp, DD, BNQ, DD, DD, 0, nullptr);
    ln_k<<<BNQ, DD, 0, s0>>>(t1, tmp, ln1_g, ln1_b, t2);

    // s0: FFN: lin1 (relu), then split-K lin2 partials + fused combine/LN3
    launch_gemm(s0, t2, nullptr, DD, lin1_w, DFF, lin1_b, ffh, DFF, BNQ, DFF, DD, 1, nullptr);
    {
        dim3 grid(DD / BN, (BNQ + BM - 1) / BM, KSPL);
        gemm_tc<0, 0, 0, KSPL><<<grid, 256, 0, s0>>>(
            ffh, nullptr, DFF, lin2_w, DD, nullptr, partb, DD,
            BNQ, DD, DFF / KSPL, nullptr);
    }
    ln_comb_k<<<BNQ, DD, 0, s0>>>(t2, partb, lin2_b, ln3_g, ln3_b, out);
}

// round 17
// speedup vs baseline: 1.3144x; 1.0244x over previous
#include <cuda_runtime.h>
#include <math.h>
#include <stdint.h>

// ---------------- problem constants ----------------
#define BB   4
#define NQ   900
#define DD   256
#define HH   8
#define HDD  32
#define LL   4
#define PP   4
#define SS   21760          // 128^2+64^2+32^2+16^2
#define DFF  1024
#define BNQ  (BB*NQ)        // 3600
#define KSPL 4              // split-K factor for lin2

// ---------------- device scratch ----------------
__device__ float g_qk [BNQ*512];
__device__ float g_v  [BNQ*DD];
__device__ float g_sa [BNQ*DD];
__device__ float g_t1 [BNQ*DD];
__device__ float g_t2 [BNQ*DD];
__device__ float g_off[BNQ*DD];
__device__ float g_acc[BNQ*DD];
__device__ float g_aw [BNQ*128];
__device__ float g_val[(long)BB*SS*DD];
__device__ float g_ffh[BNQ*DFF];
__device__ float g_part[(long)KSPL*BNQ*DD];

// ---------------- tf32 helpers ----------------
__device__ __forceinline__ float to_tf32(float x) {
    uint32_t o;
    asm("cvt.rna.tf32.f32 %0, %1;" : "=r"(o) : "f"(x));
    return __uint_as_float(o);
}

__device__ __forceinline__ void mma_tf32(float c[4],
                                         uint32_t a0, uint32_t a1, uint32_t a2, uint32_t a3,
                                         uint32_t b0, uint32_t b1) {
    asm volatile(
        "mma.sync.aligned.m16n8k8.row.col.f32.tf32.tf32.f32 "
        "{%0,%1,%2,%3}, {%4,%5,%6,%7}, {%8,%9}, {%0,%1,%2,%3};\n"
        : "+f"(c[0]), "+f"(c[1]), "+f"(c[2]), "+f"(c[3])
        : "r"(a0), "r"(a1), "r"(a2), "r"(a3), "r"(b0), "r"(b1));
}

// ---------------- TF32 GEMM (R12-proven) + optional split-K partial mode ----------------
#define BM 128
#define BN 128
#define BKg 16
#define LDS_P 136   // ==8 mod 32 -> conflict-free fragment reads

template<int RELU, int MASK, int ADDA, int SPLITK>
__global__ void __launch_bounds__(256, 2)
gemm_tc(const float* __restrict__ A, const float* __restrict__ A2, int lda,
        const float* __restrict__ W, int ldw,
        const float* __restrict__ bias,
        float* __restrict__ C, int ldc,
        int M, int N, int K,
        const unsigned char* __restrict__ mask) {
    __shared__ float As[2][BKg][LDS_P];
    __shared__ float Bs[2][BKg][LDS_P];

    if (SPLITK > 1) {
        int z = blockIdx.z;
        A += (long)z * K;
        W += (long)z * K * ldw;
        C += (long)z * M * ldc;
    }

    const int t    = threadIdx.x;
    const int lane = t & 31;
    const int wid  = t >> 5;
    const int warpM = (wid >> 1) * 32;
    const int warpN = (wid & 1) * 64;
    const int m0b = blockIdx.y * BM;
    const int n0b = blockIdx.x * BN;

    float acc[2][8][4];
    #pragma unroll
    for (int i = 0; i < 2; i++)
        #pragma unroll
        for (int j = 0; j < 8; j++)
            #pragma unroll
            for (int r = 0; r < 4; r++) acc[i][j][r] = 0.f;

    const int arow = t >> 1;
    const int akq  = (t & 1) * 8;
    const int brow = t >> 5;
    const int bcol = (t & 31) * 4;

    float4 ra1, ra2, rb1, rb2;

    auto ldg = [&](int k0) {
        ra1 = make_float4(0.f, 0.f, 0.f, 0.f); ra2 = ra1;
        int gm = m0b + arow;
        if (gm < M) {
            const float* p = A + (long)gm * lda + k0 + akq;
            ra1 = *(const float4*)p;
            ra2 = *(const float4*)(p + 4);
            if (ADDA) {
                const float* p2 = A2 + (long)gm * lda + k0 + akq;
                float4 s1 = *(const float4*)p2;
                float4 s2 = *(const float4*)(p2 + 4);
                ra1.x += s1.x; ra1.y += s1.y; ra1.z += s1.z; ra1.w += s1.w;
                ra2.x += s2.x; ra2.y += s2.y; ra2.z += s2.z; ra2.w += s2.w;
            }
        }
        rb1 = *(const float4*)(W + (long)(k0 + brow    ) * ldw + n0b + bcol);
        rb2 = *(const float4*)(W + (long)(k0 + brow + 8) * ldw + n0b + bcol);
    };

    auto sts = [&](int s) {
        As[s][akq + 0][arow] = to_tf32(ra1.x);
        As[s][akq + 1][arow] = to_tf32(ra1.y);
        As[s][akq + 2][arow] = to_tf32(ra1.z);
        As[s][akq + 3][arow] = to_tf32(ra1.w);
        As[s][akq + 4][arow] = to_tf32(ra2.x);
        As[s][akq + 5][arow] = to_tf32(ra2.y);
        As[s][akq + 6][arow] = to_tf32(ra2.z);
        As[s][akq + 7][arow] = to_tf32(ra2.w);
        float4 g1, g2;
        g1.x = to_tf32(rb1.x); g1.y = to_tf32(rb1.y);
        g1.z = to_tf32(rb1.z); g1.w = to_tf32(rb1.w);
        g2.x = to_tf32(rb2.x); g2.y = to_tf32(rb2.y);
        g2.z = to_tf32(rb2.z); g2.w = to_tf32(rb2.w);
        *(float4*)&Bs[s][brow    ][bcol] = g1;
        *(float4*)&Bs[s][brow + 8][bcol] = g2;
    };

    const int nt = K / BKg;
    ldg(0);
    sts(0);
    if (nt > 1) ldg(BKg);
    __syncthreads();

    int s = 0;
    for (int it = 0; it < nt; it++) {
        #pragma unroll
        for (int ks = 0; ks < 2; ks++) {
            const int kr = ks * 8 + (lane & 3);
            const int mo = warpM + (lane >> 2);
            uint32_t af[2][4];
            #pragma unroll
            for (int i = 0; i < 2; i++) {
                af[i][0] = __float_as_uint(As[s][kr    ][mo + 16 * i    ]);
                af[i][1] = __float_as_uint(As[s][kr    ][mo + 16 * i + 8]);
                af[i][2] = __float_as_uint(As[s][kr + 4][mo + 16 * i    ]);
                af[i][3] = __float_as_uint(As[s][kr + 4][mo + 16 * i + 8]);
            }
            uint32_t bf[8][2];
            const int no = warpN + (lane >> 2);
            #pragma unroll
            for (int j = 0; j < 8; j++) {
                bf[j][0] = __float_as_uint(Bs[s][kr    ][no + 8 * j]);
                bf[j][1] = __float_as_uint(Bs[s][kr + 4][no + 8 * j]);
            }
            #pragma unroll
            for (int i = 0; i < 2; i++)
                #pragma unroll
                for (int j = 0; j < 8; j++)
                    mma_tf32(acc[i][j], af[i][0], af[i][1], af[i][2], af[i][3],
                             bf[j][0], bf[j][1]);
        }
        if (it + 1 < nt) sts(s ^ 1);
        __syncthreads();
        if (it + 2 < nt) ldg((it + 2) * BKg);
        s ^= 1;
    }

    #pragma unroll
    for (int i = 0; i < 2; i++) {
        #pragma unroll
        for (int half = 0; half < 2; half++) {
            int gm = m0b + warpM + 16 * i + (lane >> 2) + half * 8;
            if (gm >= M) continue;
            bool mz = MASK ? (mask[gm] != 0) : false;
            #pragma unroll
            for (int j = 0; j < 8; j++) {
                int gn = n0b + warpN + 8 * j + 2 * (lane & 3);
                float v0 = acc[i][j][half * 2 + 0];
                float v1 = acc[i][j][half * 2 + 1];
                if (SPLITK == 1) {
                    v0 += bias[gn];
                    v1 += bias[gn + 1];
                    if (RELU) { v0 = fmaxf(v0, 0.f); v1 = fmaxf(v1, 0.f); }
                    if (mz)   { v0 = 0.f; v1 = 0.f; }
                }
                *(float2*)(C + (long)gm * ldc + gn) = make_float2(v0, v1);
            }
        }
    }
}

// ---------------- tensor-core flash attention: double-buffered K/V ----------------
#define KS_STRIDE 68
#define VS_STRIDE 40
#define PS_STRIDE 68
#define ATTN_SMEM ((2*64*KS_STRIDE + 2*64*VS_STRIDE + 8*16*PS_STRIDE) * 4)
#define NT_TILES ((NQ + 63) / 64)   // 15

__global__ void __launch_bounds__(256)
attn_tc(const float* __restrict__ qm, const float* __restrict__ km,
        const float* __restrict__ vm, float* __restrict__ sa) {
    extern __shared__ float dynsm[];
    float (*Ks)[64][KS_STRIDE] = (float (*)[64][KS_STRIDE])dynsm;
    float (*Vs)[64][VS_STRIDE] =
        (float (*)[64][VS_STRIDE])(dynsm + 2 * 64 * KS_STRIDE);
    float (*Ps)[16][PS_STRIDE] =
        (float (*)[16][PS_STRIDE])(dynsm + 2 * 64 * KS_STRIDE + 2 * 64 * VS_STRIDE);

    const int bh = blockIdx.y;
    const int b = bh >> 3, h = bh & 7;
    const int t = threadIdx.x;
    const int w = t >> 5, lane = t & 31;
    const int l4 = lane & 3, l2 = lane >> 2;
    const int qbase = blockIdx.x * 128 + w * 16;
    const float sc = 0.17677669529663687f;

    // loader indices (per thread): two (row, c4) elements
    const int lrow0 = t >> 3,          lc0 = (t & 7) * 4;
    const int lrow1 = (t + 256) >> 3,  lc1 = lc0;

    uint32_t aq[4][4];
    {
        int r0 = min(qbase + l2,     NQ - 1);
        int r1 = min(qbase + l2 + 8, NQ - 1);
        const float* q0 = qm + ((long)(b * NQ + r0)) * 512 + h * HDD;
        const float* q1 = qm + ((long)(b * NQ + r1)) * 512 + h * HDD;
        #pragma unroll
        for (int ks = 0; ks < 4; ks++) {
            int c = ks * 8 + l4;
            aq[ks][0] = __float_as_uint(to_tf32(q0[c]));
            aq[ks][1] = __float_as_uint(to_tf32(q1[c]));
            aq[ks][2] = __float_as_uint(to_tf32(q0[c + 4]));
            aq[ks][3] = __float_as_uint(to_tf32(q1[c + 4]));
        }
    }

    float4 kreg[2], vreg[2];
    auto ldg = [&](int tile) {
        int kc = tile * 64;
        int jg0 = min(kc + lrow0, NQ - 1);
        int jg1 = min(kc + lrow1, NQ - 1);
        kreg[0] = *(const float4*)(km + ((long)(b * NQ + jg0)) * 512 + h * HDD + lc0);
        vreg[0] = *(const float4*)(vm + ((long)(b * NQ + jg0)) * DD  + h * HDD + lc0);
        kreg[1] = *(const float4*)(km + ((long)(b * NQ + jg1)) * 512 + h * HDD + lc1);
        vreg[1] = *(const float4*)(vm + ((long)(b * NQ + jg1)) * DD  + h * HDD + lc1);
    };
    auto sts = [&](int s) {
        float4 kt, vt;
        kt.x = to_tf32(kreg[0].x); kt.y = to_tf32(kreg[0].y);
        kt.z = to_tf32(kreg[0].z); kt.w = to_tf32(kreg[0].w);
        vt.x = to_tf32(vreg[0].x); vt.y = to_tf32(vreg[0].y);
        vt.z = to_tf32(vreg[0].z); vt.w = to_tf32(vreg[0].w);
        *(float4*)&Ks[s][lrow0][lc0] = kt;
        *(float4*)&Vs[s][lrow0][lc0] = vt;
        kt.x = to_tf32(kreg[1].x); kt.y = to_tf32(kreg[1].y);
        kt.z = to_tf32(kreg[1].z); kt.w = to_tf32(kreg[1].w);
        vt.x = to_tf32(vreg[1].x); vt.y = to_tf32(vreg[1].y);
        vt.z = to_tf32(vreg[1].z); vt.w = to_tf32(vreg[1].w);
        *(float4*)&Ks[s][lrow1][lc1] = kt;
        *(float4*)&Vs[s][lrow1][lc1] = vt;
    };

    float m0 = -1e30f, m1 = -1e30f, l0 = 0.f, l1 = 0.f;
    float O[4][4];
    #pragma unroll
    for (int i = 0; i < 4; i++)
        #pragma unroll
        for (int r = 0; r < 4; r++) O[i][r] = 0.f;

    ldg(0);
    sts(0);
    if (NT_TILES > 1) ldg(1);
    __syncthreads();

    int sb = 0;
    for (int it = 0; it < NT_TILES; it++) {
        const int kc = it * 64;

        // ---- S = Q K^T ----
        float s[8][4];
        #pragma unroll
        for (int nt = 0; nt < 8; nt++) {
            #pragma unroll
            for (int r = 0; r < 4; r++) s[nt][r] = 0.f;
            #pragma unroll
            for (int ks = 0; ks < 4; ks++) {
                int d = ks * 8 + l4;
                uint32_t b0 = __float_as_uint(Ks[sb][nt * 8 + l2][d]);
                uint32_t b1 = __float_as_uint(Ks[sb][nt * 8 + l2][d + 4]);
                mma_tf32(s[nt], aq[ks][0], aq[ks][1], aq[ks][2], aq[ks][3], b0, b1);
            }
        }

        const int jmax = NQ - kc;
        if (jmax >= 64) {
            #pragma unroll
            for (int nt = 0; nt < 8; nt++)
                #pragma unroll
                for (int r = 0; r < 4; r++) s[nt][r] *= sc;
        } else {
            #pragma unroll
            for (int nt = 0; nt < 8; nt++)
                #pragma unroll
                for (int r = 0; r < 4; r++) {
                    int col = nt * 8 + 2 * l4 + (r & 1);
                    s[nt][r] = (col < jmax) ? s[nt][r] * sc : -1e30f;
                }
        }

        // ---- online softmax ----
        float mx0 = -1e30f, mx1 = -1e30f;
        #pragma unroll
        for (int nt = 0; nt < 8; nt++) {
            mx0 = fmaxf(mx0, fmaxf(s[nt][0], s[nt][1]));
            mx1 = fmaxf(mx1, fmaxf(s[nt][2], s[nt][3]));
        }
        mx0 = fmaxf(mx0, __shfl_xor_sync(0xffffffffu, mx0, 1));
        mx0 = fmaxf(mx0, __shfl_xor_sync(0xffffffffu, mx0, 2));
        mx1 = fmaxf(mx1, __shfl_xor_sync(0xffffffffu, mx1, 1));
        mx1 = fmaxf(mx1, __shfl_xor_sync(0xffffffffu, mx1, 2));

        float nm0 = fmaxf(m0, mx0), nm1 = fmaxf(m1, mx1);
        float cor0 = __expf(m0 - nm0), cor1 = __expf(m1 - nm1);
        m0 = nm0; m1 = nm1;

        float rs0 = 0.f, rs1 = 0.f;
        #pragma unroll
        for (int nt = 0; nt < 8; nt++) {
            float p0 = __expf(s[nt][0] - nm0);
            float p1 = __expf(s[nt][1] - nm0);
            float p2 = __expf(s[nt][2] - nm1);
            float p3 = __expf(s[nt][3] - nm1);
            rs0 += p0 + p1;
            rs1 += p2 + p3;
            int colb = nt * 8 + 2 * l4;
            *(float2*)&Ps[w][l2    ][colb] = make_float2(p0, p1);
            *(float2*)&Ps[w][l2 + 8][colb] = make_float2(p2, p3);
        }
        rs0 += __shfl_xor_sync(0xffffffffu, rs0, 1);
        rs0 += __shfl_xor_sync(0xffffffffu, rs0, 2);
        rs1 += __shfl_xor_sync(0xffffffffu, rs1, 1);
        rs1 += __shfl_xor_sync(0xffffffffu, rs1, 2);
        l0 = l0 * cor0 + rs0;
        l1 = l1 * cor1 + rs1;

        #pragma unroll
        for (int i = 0; i < 4; i++) {
            O[i][0] *= cor0; O[i][1] *= cor0;
            O[i][2] *= cor1; O[i][3] *= cor1;
        }
        __syncwarp();

        // ---- O += P V ----
        #pragma unroll
        for (int ks2 = 0; ks2 < 8; ks2++) {
            int colb = ks2 * 8 + l4;
            uint32_t a0 = __float_as_uint(Ps[w][l2    ][colb]);
            uint32_t a1 = __float_as_uint(Ps[w][l2 + 8][colb]);
            uint32_t a2 = __float_as_uint(Ps[w][l2    ][colb + 4]);
            uint32_t a3 = __float_as_uint(Ps[w][l2 + 8][colb + 4]);
            #pragma unroll
            for (int nt2 = 0; nt2 < 4; nt2++) {
                uint32_t b0 = __float_as_uint(Vs[sb][ks2 * 8 + l4    ][nt2 * 8 + l2]);
                uint32_t b1 = __float_as_uint(Vs[sb][ks2 * 8 + l4 + 4][nt2 * 8 + l2]);
                mma_tf32(O[nt2], a0, a1, a2, a3, b0, b1);
            }
        }

        if (it + 1 < NT_TILES) sts(sb ^ 1);
        __syncthreads();
        if (it + 2 < NT_TILES) ldg(it + 2);
        sb ^= 1;
    }

    float inv0 = 1.f / l0, inv1 = 1.f / l1;
    int q0 = qbase + l2, q1 = qbase + l2 + 8;
    if (q0 < NQ) {
        float* o0 = sa + ((long)(b * NQ + q0)) * DD + h * HDD;
        #pragma unroll
        for (int nt2 = 0; nt2 < 4; nt2++)
            *(float2*)(o0 + nt2 * 8 + 2 * l4) = make_float2(O[nt2][0] * inv0, O[nt2][1] * inv0);
    }
    if (q1 < NQ) {
        float* o1 = sa + ((long)(b * NQ + q1)) * DD + h * HDD;
        #pragma unroll
        for (int nt2 = 0; nt2 < 4; nt2++)
            *(float2*)(o1 + nt2 * 8 + 2 * l4) = make_float2(O[nt2][2] * inv1, O[nt2][3] * inv1);
    }
}

// ---------------- split-K combine + bias + residual + LayerNorm ----------------
template<int Z>
__global__ void ln_comb_k(const float* __restrict__ resid,
                          const float* __restrict__ part,
                          const float* __restrict__ bias,
                          const float* __restrict__ g, const float* __restrict__ bta,
                          float* __restrict__ out) {
    const int r = blockIdx.x, tdx = threadIdx.x;
    const int wid = tdx >> 5, lane = tdx & 31;
    __shared__ float red[8];
    __shared__ float s_mean, s_rstd;

    float x = resid[(long)r * DD + tdx] + bias[tdx];
    #pragma unroll
    for (int z = 0; z < Z; z++)
        x += part[(long)z * BNQ * DD + (long)r * DD + tdx];

    float s = x;
    #pragma unroll
    for (int o = 16; o; o >>= 1) s += __shfl_xor_sync(0xffffffffu, s, o);
    if (lane == 0) red[wid] = s;
    __syncthreads();
    if (tdx == 0) {
        float tot = 0.f;
        #pragma unroll
        for (int i = 0; i < 8; i++) tot += red[i];
        s_mean = tot * (1.f / DD);
    }
    __syncthreads();
    float mean = s_mean;
    float dx = x - mean;

    float s2 = dx * dx;
    #pragma unroll
    for (int o = 16; o; o >>= 1) s2 += __shfl_xor_sync(0xffffffffu, s2, o);
    if (lane == 0) red[wid] = s2;
    __syncthreads();
    if (tdx == 0) {
        float tot = 0.f;
        #pragma unroll
        for (int i = 0; i < 8; i++) tot += red[i];
        s_rstd = rsqrtf(tot * (1.f / DD) + 1e-5f);
    }
    __syncthreads();
    out[(long)r * DD + tdx] = dx * s_rstd * g[tdx] + bta[tdx];
}

// ---------------- attention-weight softmax over 16 ----------------
__global__ void awsm_k(float* __restrict__ aw) {
    int idx = blockIdx.x * 256 + threadIdx.x;
    if (idx >= BNQ * HH) return;
    int bq = idx >> 3, h = idx & 7;
    float* p = aw + (long)bq * 128 + h * 16;
    float m = -1e30f;
    float e[16];
    #pragma unroll
    for (int i = 0; i < 16; i++) m = fmaxf(m, p[i]);
    float sum = 0.f;
    #pragma unroll
    for (int i = 0; i < 16; i++) { e[i] = __expf(p[i] - m); sum += e[i]; }
    float inv = 1.f / sum;
    #pragma unroll
    for (int i = 0; i < 16; i++) p[i] = e[i] * inv;
}

// ---------------- deformable bilinear sampling: branchless ----------------
__global__ void samp_k(const float* __restrict__ off, const float* __restrict__ aw,
                       const float* __restrict__ refp, const float* __restrict__ val,
                       float* __restrict__ acc) {
    const int widx = blockIdx.x * 8 + (threadIdx.x >> 5);
    const int lane = threadIdx.x & 31;
    if (widx >= BNQ * HH) return;
    const int b = widx / (NQ * HH);
    const int rem = widx % (NQ * HH);
    const int qI = rem / HH, h = rem % HH;

    const int dims[4]   = {128, 64, 32, 16};
    const int starts[4] = {0, 16384, 20480, 21504};

    const long obase = ((long)(b * NQ + qI)) * DD + h * HDD;
    const long abase = ((long)(b * NQ + qI)) * 128 + h * 16;
    const float* vb = val + ((long)b * SS) * DD + h * HDD + lane;

    float a = 0.f;
    #pragma unroll
    for (int l = 0; l < 4; l++) {
        const int Wl = dims[l], st = starts[l];
        const float rx = refp[(((long)(b * NQ + qI)) * LL + l) * 2 + 0];
        const float ry = refp[(((long)(b * NQ + qI)) * LL + l) * 2 + 1];
        #pragma unroll
        for (int p = 0; p < 4; p++) {
            float x = rx * Wl + off[obase + l * 8 + p * 2 + 0] - 0.5f;
            float y = ry * Wl + off[obase + l * 8 + p * 2 + 1] - 0.5f;
            float x0f = floorf(x), y0f = floorf(y);
            int x0 = (int)x0f, y0 = (int)y0f;
            int x1 = x0 + 1,   y1 = y0 + 1;
            float wx = x - x0f, wy = y - y0f;
            float w = aw[abase + l * 4 + p];

            float vx0 = (x0 >= 0 && x0 < Wl) ? 1.f : 0.f;
            float vx1 = (x1 >= 0 && x1 < Wl) ? 1.f : 0.f;
            float vy0 = (y0 >= 0 && y0 < Wl) ? 1.f : 0.f;
            float vy1 = (y1 >= 0 && y1 < Wl) ? 1.f : 0.f;
            int x0c = min(max(x0, 0), Wl - 1);
            int x1c = min(max(x1, 0), Wl - 1);
            int y0c = min(max(y0, 0), Wl - 1);
            int y1c = min(max(y1, 0), Wl - 1);

            float c00 = w * (1.f - wx) * (1.f - wy) * vx0 * vy0;
            float c10 = w * wx * (1.f - wy) * vx1 * vy0;
            float c01 = w * (1.f - wx) * wy * vx0 * vy1;
            float c11 = w * wx * wy * vx1 * vy1;

            const float* base = vb + (long)st * DD;
            float v00 = base[((long)y0c * Wl + x0c) * DD];
            float v10 = base[((long)y0c * Wl + x1c) * DD];
            float v01 = base[((long)y1c * Wl + x0c) * DD];
            float v11 = base[((long)y1c * Wl + x1c) * DD];

            a = fmaf(c00, v00, a);
            a = fmaf(c10, v10, a);
            a = fmaf(c01, v01, a);
            a = fmaf(c11, v11, a);
        }
    }
    acc[obase + lane] = a;
}

// ---------------- host launch ----------------
static inline void launch_gemm(cudaStream_t st,
                               const float* A, const float* A2, int lda,
                               const float* W, int ldw,
                               const float* bias, float* C, int ldc,
                               int M, int N, int K,
                               int relu, const unsigned char* mask) {
    dim3 grid(N / BN, (M + BM - 1) / BM);
    if (mask)
        gemm_tc<0, 1, 0, 1><<<grid, 256, 0, st>>>(A, nullptr, lda, W, ldw, bias, C, ldc, M, N, K, mask);
    else if (relu)
        gemm_tc<1, 0, 0, 1><<<grid, 256, 0, st>>>(A, nullptr, lda, W, ldw, bias, C, ldc, M, N, K, nullptr);
    else if (A2)
        gemm_tc<0, 0, 1, 1><<<grid, 256, 0, st>>>(A, A2, lda, W, ldw, bias, C, ldc, M, N, K, nullptr);
    else
        gemm_tc<0, 0, 0, 1><<<grid, 256, 0, st>>>(A, nullptr, lda, W, ldw, bias, C, ldc, M, N, K, nullptr);
}

extern "C" void kernel_launch(void* const* d_in, const int* in_sizes, int n_in,
                              void* d_out, int out_size) {
    const float* tgt        = (const float*)d_in[0];
    const float* query_pos  = (const float*)d_in[1];
    const float* refp       = (const float*)d_in[2];
    const float* memory     = (const float*)d_in[3];
    const float* in_proj_w  = (const float*)d_in[4];
    const float* in_proj_b  = (const float*)d_in[5];
    const float* out_proj_w = (const float*)d_in[6];
    const float* out_proj_b = (const float*)d_in[7];
    const float* ln1_g      = (const float*)d_in[8];
    const float* ln1_b      = (const float*)d_in[9];
    const float* ln2_g      = (const float*)d_in[10];
    const float* ln2_b      = (const float*)d_in[11];
    const float* ln3_g      = (const float*)d_in[12];
    const float* ln3_b      = (const float*)d_in[13];
    const float* vproj_w    = (const float*)d_in[14];
    const float* vproj_b    = (const float*)d_in[15];
    const float* off_w      = (const float*)d_in[16];
    const float* off_b      = (const float*)d_in[17];
    const float* aw_w       = (const float*)d_in[18];
    const float* aw_b       = (const float*)d_in[19];
    const float* oproj_w    = (const float*)d_in[20];
    const float* oproj_b    = (const float*)d_in[21];
    const float* lin1_w     = (const float*)d_in[22];
    const float* lin1_b     = (const float*)d_in[23];
    const float* lin2_w     = (const float*)d_in[24];
    const float* lin2_b     = (const float*)d_in[25];
    const unsigned char* mem_mask = (const unsigned char*)d_in[27];
    float* out = (float*)d_out;

    float *qk, *v, *sa, *t1, *t2, *offb, *accb, *awb, *valb, *ffh, *partb;
    cudaGetSymbolAddress((void**)&qk,  g_qk);
    cudaGetSymbolAddress((void**)&v,   g_v);
    cudaGetSymbolAddress((void**)&sa,  g_sa);
    cudaGetSymbolAddress((void**)&t1,  g_t1);
    cudaGetSymbolAddress((void**)&t2,  g_t2);
    cudaGetSymbolAddress((void**)&offb, g_off);
    cudaGetSymbolAddress((void**)&accb, g_acc);
    cudaGetSymbolAddress((void**)&awb,  g_aw);
    cudaGetSymbolAddress((void**)&valb, g_val);
    cudaGetSymbolAddress((void**)&ffh,  g_ffh);
    cudaGetSymbolAddress((void**)&partb, g_part);

    static int inited = 0;
    static cudaStream_t s2, s3;
    static cudaEvent_t evFork, evV, evVal, evAw;
    if (!inited) {
        cudaFuncSetAttribute(attn_tc, cudaFuncAttributeMaxDynamicSharedMemorySize,
                             ATTN_SMEM);
        cudaStreamCreateWithFlags(&s2, cudaStreamNonBlocking);
        cudaStreamCreateWithFlags(&s3, cudaStreamNonBlocking);
        cudaEventCreateWithFlags(&evFork, cudaEventDisableTiming);
        cudaEventCreateWithFlags(&evV,    cudaEventDisableTiming);
        cudaEventCreateWithFlags(&evVal,  cudaEventDisableTiming);
        cudaEventCreateWithFlags(&evAw,   cudaEventDisableTiming);
        inited = 1;
    }

    cudaStream_t s0 = 0;

    // fork s2
    cudaEventRecord(evFork, s0);
    cudaStreamWaitEvent(s2, evFork, 0);

    // s0: fused q|k projection (A = tgt + query_pos)
    launch_gemm(s0, tgt, query_pos, DD, in_proj_w, 3 * DD, in_proj_b, qk, 512, BNQ, 512, DD, 0, nullptr);

    // s2: v projection, then big value projection
    launch_gemm(s2, tgt, nullptr, DD, in_proj_w + 2 * DD, 3 * DD, in_proj_b + 2 * DD, v, DD, BNQ, DD, DD, 0, nullptr);
    cudaEventRecord(evV, s2);
    launch_gemm(s2, memory, nullptr, DD, vproj_w, DD, vproj_b, valb, DD, BB * SS, DD, DD, 0, mem_mask);
    cudaEventRecord(evVal, s2);

    // s0: attention
    cudaStreamWaitEvent(s0, evV, 0);
    attn_tc<<<dim3((NQ + 127) / 128, BB * HH), 256, ATTN_SMEM, s0>>>(qk, qk + 256, v, sa);

    // s0: out_proj (split-K=2) + fused combine/LN2 -> t1
    {
        dim3 grid(DD / BN, (BNQ + BM - 1) / BM, 2);
        gemm_tc<0, 0, 0, 2><<<grid, 256, 0, s0>>>(
            sa, nullptr, DD, out_proj_w, DD, nullptr, partb, DD, BNQ, DD, DD / 2, nullptr);
    }
    ln_comb_k<2><<<BNQ, DD, 0, s0>>>(tgt, partb, out_proj_b, ln2_g, ln2_b, t1);

    // fork s3: aw gemm + softmax
    cudaEventRecord(evFork, s0);
    cudaStreamWaitEvent(s3, evFork, 0);
    launch_gemm(s3, t1, query_pos, DD, aw_w, 128, aw_b, awb, 128, BNQ, 128, DD, 0, nullptr);
    awsm_k<<<(BNQ * HH + 255) / 256, 256, 0, s3>>>(awb);
    cudaEventRecord(evAw, s3);

    // s0: off gemm
    launch_gemm(s0, t1, query_pos, DD, off_w, DD, off_b, offb, DD, BNQ, DD, DD, 0, nullptr);

    // s0: sampling
    cudaStreamWaitEvent(s0, evAw, 0);
    cudaStreamWaitEvent(s0, evVal, 0);
    samp_k<<<(BNQ * HH) / 8, 256, 0, s0>>>(offb, awb, refp, valb, accb);

    // s0: output projection (split-K=2) + fused combine/LN1 -> t2
    {
        dim3 grid(DD / BN, (BNQ + BM - 1) / BM, 2);
        gemm_tc<0, 0, 0, 2><<<grid, 256, 0, s0>>>(
            accb, nullptr, DD, oproj_w, DD, nullptr, partb, DD, BNQ, DD, DD / 2, nullptr);
    }
    ln_comb_k<2><<<BNQ, DD, 0, s0>>>(t1, partb, oproj_b, ln1_g, ln1_b, t2);

    // s0: FFN: lin1 (relu), then split-K lin2 partials + fused combine/LN3
    launch_gemm(s0, t2, nullptr, DD, lin1_w, DFF, lin1_b, ffh, DFF, BNQ, DFF, DD, 1, nullptr);
    {
        dim3 grid(DD / BN, (BNQ + BM - 1) / BM, KSPL);
        gemm_tc<0, 0, 0, KSPL><<<grid, 256, 0, s0>>>(
            ffh, nullptr, DFF, lin2_w, DD, nullptr, partb, DD,
            BNQ, DD, DFF / KSPL, nullptr);
    }
    ln_comb_k<KSPL><<<BNQ, DD, 0, s0>>>(t2, partb, lin2_b, ln3_g, ln3_b, out);
}